// round 1
// baseline (speedup 1.0000x reference)
#include <cuda_runtime.h>

#define NC 200
#define NA 768
#define NB 256

// ---------------- scratch (static device globals; no allocs) ----------------
__device__ int   g_cnt[NC];
__device__ int   g_items[NC * 256];
__device__ float g_w[NC];
__device__ float g_ave[NC * NA];
__device__ float g_dvec[NC * NA];
__device__ float g_qcov[2 * NC * NC];   // [m][c][c'] quadratic forms vs original CoV
__device__ float g_qlow[2 * NC * NC];   // low-rank contributions of new_CoV
__device__ float g_ce[NB];
__device__ float g_kl[NB];

// ---------------- per-class stats: counts, buckets, ave, w, dvec ------------
__global__ void k_stats(const float* __restrict__ feat, const float* __restrict__ Ave,
                        const float* __restrict__ Amount, const int* __restrict__ tgt) {
    int c = blockIdx.x;
    __shared__ int s_cnt;
    if (threadIdx.x == 0) {
        int k = 0;
        for (int n = 0; n < NB; ++n)
            if (tgt[n] == c) g_items[c * 256 + (k++)] = n;   // ascending n: deterministic
        s_cnt = k;
        g_cnt[c] = k;
        float amt = (float)k;
        float den = amt + Amount[c];
        g_w[c] = (den > 0.f) ? (amt / den) : 0.f;
    }
    __syncthreads();
    int cnt = s_cnt;
    float inv = 1.f / fmaxf((float)cnt, 1.f);
    for (int a = threadIdx.x; a < NA; a += blockDim.x) {
        float s = 0.f;
        for (int k = 0; k < cnt; ++k) s += feat[g_items[c * 256 + k] * NA + a];
        float av = s * inv;
        g_ave[c * NA + a]  = av;
        g_dvec[c * NA + a] = Ave[c * NA + a] - av;
    }
}

// ---------------- y = feat @ w_fc^T + b_fc  -> out[1:] ----------------------
__global__ void k_y(const float* __restrict__ feat, const float* __restrict__ wfc,
                    const float* __restrict__ bfc, float* __restrict__ out) {
    int n = blockIdx.x;
    __shared__ float sf[NA];
    for (int a = threadIdx.x; a < NA; a += blockDim.x) sf[a] = feat[n * NA + a];
    __syncthreads();
    int lane = threadIdx.x & 31, wid = threadIdx.x >> 5;
    for (int c = wid; c < NC; c += 8) {
        float acc = 0.f;
        for (int a = lane; a < NA; a += 32) acc += sf[a] * wfc[c * NA + a];
        #pragma unroll
        for (int o = 16; o; o >>= 1) acc += __shfl_xor_sync(0xffffffffu, acc, o);
        if (lane == 0) out[1 + n * NC + c] = acc + bfc[c];
    }
}

// ---------------- low-rank part of  dw^T new_CoV dw -------------------------
// qlow[c,c'] = (w/amt) * sum_k (dw·u_k)^2 + w(1-w)*(dw·dvec)^2
__global__ void k_lowrank(const float* __restrict__ feat, const float* __restrict__ wfc,
                          const float* __restrict__ wfct) {
    int c = blockIdx.x;
    int cnt = g_cnt[c];
    if (cnt == 0) return;
    float w = g_w[c];
    float amt = (float)cnt;
    int lane = threadIdx.x & 31, wid = threadIdx.x >> 5;
    for (int idx = wid; idx < 2 * NC; idx += (int)(blockDim.x >> 5)) {
        const float* W = (idx < NC) ? wfc : wfct;
        int cp = (idx < NC) ? idx : idx - NC;
        float ssum = 0.f, dd = 0.f;
        for (int v = 0; v <= cnt; ++v) {
            float acc = 0.f;
            if (v < cnt) {
                const float* f = feat + g_items[c * 256 + v] * NA;
                for (int a = lane; a < NA; a += 32)
                    acc += (W[cp * NA + a] - W[c * NA + a]) * (f[a] - g_ave[c * NA + a]);
            } else {
                for (int a = lane; a < NA; a += 32)
                    acc += (W[cp * NA + a] - W[c * NA + a]) * g_dvec[c * NA + a];
            }
            #pragma unroll
            for (int o = 16; o; o >>= 1) acc += __shfl_xor_sync(0xffffffffu, acc, o);
            if (v < cnt) ssum += acc * acc; else dd = acc * acc;
        }
        if (lane == 0) {
            int m = (idx < NC) ? 0 : 1;
            g_qlow[m * NC * NC + c * NC + cp] = (w / amt) * ssum + w * (1.f - w) * dd;
        }
    }
}

// ---------------- heavy kernel: qcov[m][c][c'] = dw^T CoV[c] dw -------------
// Per (class, row-tile): G = D * M  (D=[128,768] shifted weight rows, M=CoV[c])
// fused with row-wise dot against D. 8x8 register tile, 128x128x16 smem tiles.
#define TR 128
#define TRP 132
#define TB 128
#define KA 16

__global__ __launch_bounds__(256, 2) void k_qcov(const float* __restrict__ CoV,
                                                 const float* __restrict__ wfc,
                                                 const float* __restrict__ wfct) {
    int c = blockIdx.x;
    if (g_cnt[c] == 0) return;
    int r0 = blockIdx.y * TR;
    int tid = threadIdx.x;
    int tx = tid & 15, ty = tid >> 4;

    __shared__ __align__(16) float sD[KA][TRP];
    __shared__ __align__(16) float sM[KA][TB];
    __shared__ float sQ[TR][16];

    const float* covc = CoV + (size_t)c * NA * NA;
    const float* wcf  = wfc  + c * NA;
    const float* wcft = wfct + c * NA;

    float qth[8];
    #pragma unroll
    for (int i = 0; i < 8; ++i) qth[i] = 0.f;

    for (int b0 = 0; b0 < NA; b0 += TB) {
        float acc[8][8];
        #pragma unroll
        for (int i = 0; i < 8; ++i)
            #pragma unroll
            for (int j = 0; j < 8; ++j) acc[i][j] = 0.f;

        for (int a0 = 0; a0 < NA; a0 += KA) {
            // D tile: sD[a][r] = W[r0+r][a0+a] - Wclass[a0+a]   (0 beyond 400 rows)
            #pragma unroll
            for (int p = 0; p < 8; ++p) {
                int idx = tid + p * 256;
                int a = idx & 15;
                int r = idx >> 4;
                int gr = r0 + r;
                float v = 0.f;
                if (gr < 2 * NC) {
                    const float* W  = (gr < NC) ? wfc : wfct;
                    const float* Wc = (gr < NC) ? wcf : wcft;
                    int rr = (gr < NC) ? gr : gr - NC;
                    v = W[rr * NA + a0 + a] - Wc[a0 + a];
                }
                sD[a][r] = v;
            }
            // M tile: sM[a][b] = CoV[c][a0+a][b0+b]
            #pragma unroll
            for (int p = 0; p < 8; ++p) {
                int idx = tid + p * 256;
                int b = idx & 127;
                int a = idx >> 7;
                sM[a][b] = covc[(size_t)(a0 + a) * NA + b0 + b];
            }
            __syncthreads();
            #pragma unroll
            for (int aa = 0; aa < KA; ++aa) {
                float4 d0 = *(const float4*)&sD[aa][ty * 8];
                float4 d1 = *(const float4*)&sD[aa][ty * 8 + 4];
                float4 m0 = *(const float4*)&sM[aa][tx * 8];
                float4 m1 = *(const float4*)&sM[aa][tx * 8 + 4];
                float dv[8] = {d0.x, d0.y, d0.z, d0.w, d1.x, d1.y, d1.z, d1.w};
                float mv[8] = {m0.x, m0.y, m0.z, m0.w, m1.x, m1.y, m1.z, m1.w};
                #pragma unroll
                for (int i = 0; i < 8; ++i)
                    #pragma unroll
                    for (int j = 0; j < 8; ++j) acc[i][j] += dv[i] * mv[j];
            }
            __syncthreads();
        }
        // epilogue: contract this G tile with D along b
        #pragma unroll
        for (int i = 0; i < 8; ++i) {
            int gr = r0 + ty * 8 + i;
            if (gr < 2 * NC) {
                const float* W  = (gr < NC) ? wfc : wfct;
                const float* Wc = (gr < NC) ? wcf : wcft;
                int rr = (gr < NC) ? gr : gr - NC;
                #pragma unroll
                for (int j = 0; j < 8; ++j) {
                    int b = b0 + tx * 8 + j;
                    qth[i] += acc[i][j] * (W[rr * NA + b] - Wc[b]);
                }
            }
        }
    }
    // deterministic cross-tx reduction
    #pragma unroll
    for (int i = 0; i < 8; ++i) sQ[ty * 8 + i][tx] = qth[i];
    __syncthreads();
    if (tid < TR) {
        int gr = r0 + tid;
        if (gr < 2 * NC) {
            float s = 0.f;
            #pragma unroll
            for (int t = 0; t < 16; ++t) s += sQ[tid][t];
            int m  = (gr < NC) ? 0 : 1;
            int rr = (gr < NC) ? gr : gr - NC;
            g_qcov[m * NC * NC + c * NC + rr] = s;
        }
    }
}

// ---------------- per-row softmax/CE/KL -------------------------------------
__device__ __forceinline__ float blk_max(float v, float* red) {
    int t = threadIdx.x;
    red[t] = v; __syncthreads();
    for (int s = 128; s; s >>= 1) { if (t < s) red[t] = fmaxf(red[t], red[t + s]); __syncthreads(); }
    float r = red[0]; __syncthreads(); return r;
}
__device__ __forceinline__ float blk_sum(float v, float* red) {
    int t = threadIdx.x;
    red[t] = v; __syncthreads();
    for (int s = 128; s; s >>= 1) { if (t < s) red[t] += red[t + s]; __syncthreads(); }
    float r = red[0]; __syncthreads(); return r;
}

__global__ void k_loss(const float* __restrict__ out, const int* __restrict__ tgt,
                       const float* __restrict__ ratio_p) {
    int n = blockIdx.x;
    int c = threadIdx.x;
    bool valid = (c < NC);
    int yn = tgt[n];
    float wy = g_w[yn];
    float ratio = ratio_p[0];
    __shared__ float red[256];

    float aug = -1e30f, augt = -1e30f;
    if (valid) {
        float yv = out[1 + n * NC + c];
        float q1 = (1.f - wy) * g_qcov[yn * NC + c] + g_qlow[yn * NC + c];
        float q2 = (1.f - wy) * g_qcov[NC * NC + yn * NC + c] + g_qlow[NC * NC + yn * NC + c];
        aug  = yv + 0.5f * ratio * q1;
        augt = yv + 0.5f * ratio * q2;
    }
    float mx  = blk_max(aug,  red);
    float mxt = blk_max(augt, red);
    float s1 = blk_sum(valid ? expf(aug  - mx)  : 0.f, red);
    float s2 = blk_sum(valid ? expf(augt - mxt) : 0.f, red);
    float l1 = logf(s1), l2 = logf(s2);
    float lp  = aug  - mx  - l1;
    float lpt = augt - mxt - l2;
    float pt  = valid ? expf(lpt) : 0.f;
    float klterm = valid ? pt * (lpt - lp) : 0.f;
    float kln = blk_sum(klterm, red);
    if (threadIdx.x == 0) g_kl[n] = kln;
    if (valid && c == yn) g_ce[n] = -lp;
}

__global__ void k_final(float* __restrict__ out) {
    __shared__ float red[256];
    int t = threadIdx.x;
    float v = g_ce[t] * (1.f / (float)NB) + g_kl[t] * (1.f / ((float)NB * (float)NC));
    red[t] = v; __syncthreads();
    for (int s = 128; s; s >>= 1) { if (t < s) red[t] += red[t + s]; __syncthreads(); }
    if (t == 0) out[0] = red[0];
}

// ---------------- launch -----------------------------------------------------
extern "C" void kernel_launch(void* const* d_in, const int* in_sizes, int n_in,
                              void* d_out, int out_size) {
    const float* feat  = (const float*)d_in[0];
    const float* wfc   = (const float*)d_in[1];
    const float* bfc   = (const float*)d_in[2];
    const float* wfct  = (const float*)d_in[3];
    const float* cov   = (const float*)d_in[4];
    const float* Ave   = (const float*)d_in[5];
    const float* Amt   = (const float*)d_in[6];
    const int*   tgt   = (const int*)d_in[7];
    const float* ratio = (const float*)d_in[8];
    float* out = (float*)d_out;

    k_stats  <<<NC, 256>>>(feat, Ave, Amt, tgt);
    k_y      <<<NB, 256>>>(feat, wfc, bfc, out);
    k_lowrank<<<NC, 256>>>(feat, wfc, wfct);
    k_qcov   <<<dim3(NC, 4), 256>>>(cov, wfc, wfct);
    k_loss   <<<NB, 256>>>(out, tgt, ratio);
    k_final  <<<1, 256>>>(out);
}

// round 2
// speedup vs baseline: 1.9428x; 1.9428x over previous
#include <cuda_runtime.h>
#include <cuda_bf16.h>
#include <mma.h>
using namespace nvcuda;

#define NC 200
#define NA 768
#define NB 256
#define KTOT (NA * NA)          // 589824
#define KS 96                   // k-splits
#define KSPLIT (KTOT / KS)      // 6144
#define BK 64
#define NCHUNK (KSPLIT / BK)    // 96
#define BM 128
#define BN 128
#define NT 2                    // n tiles (covers 256 >= 200)
#define MPAD 512

// ---------------- scratch (static device globals; no allocs) ----------------
__device__ int   g_cnt[NC];
__device__ int   g_items[NC * 256];
__device__ float g_w[NC];
__device__ float g_ave[NC * NA];
__device__ float g_dvec[NC * NA];
__device__ float g_qcov[2 * NC * NC];
__device__ float g_qlow[2 * NC * NC];
__device__ float g_ce[NB];
__device__ float g_kl[NB];
__device__ __nv_bfloat16 g_wb[MPAD * NA];            // stacked [wfc; wfct; 0] bf16
__device__ float g_part[(size_t)KS * NT * 4 * BM * BN];  // split-K partials (50.3 MB)
__device__ float g_t1[MPAD * 256];                   // t1[r][c]
__device__ float g_u[NC * 2 * NA];                   // (M+M^T) w  per (c,m)
__device__ float g_self[NC * 2];                     // w^T M w    per (c,m)

// ---------------- per-class stats ------------------------------------------
__global__ void k_stats(const float* __restrict__ feat, const float* __restrict__ Ave,
                        const float* __restrict__ Amount, const int* __restrict__ tgt) {
    int c = blockIdx.x;
    __shared__ int s_cnt;
    if (threadIdx.x == 0) {
        int k = 0;
        for (int n = 0; n < NB; ++n)
            if (tgt[n] == c) g_items[c * 256 + (k++)] = n;
        s_cnt = k;
        g_cnt[c] = k;
        float amt = (float)k;
        float den = amt + Amount[c];
        g_w[c] = (den > 0.f) ? (amt / den) : 0.f;
    }
    __syncthreads();
    int cnt = s_cnt;
    float inv = 1.f / fmaxf((float)cnt, 1.f);
    for (int a = threadIdx.x; a < NA; a += blockDim.x) {
        float s = 0.f;
        for (int k = 0; k < cnt; ++k) s += feat[g_items[c * 256 + k] * NA + a];
        float av = s * inv;
        g_ave[c * NA + a]  = av;
        g_dvec[c * NA + a] = Ave[c * NA + a] - av;
    }
}

// ---------------- bf16 stacked weights -------------------------------------
__global__ void k_wconv(const float* __restrict__ wfc, const float* __restrict__ wfct) {
    int r = blockIdx.x;
    for (int a = threadIdx.x; a < NA; a += blockDim.x) {
        float v = 0.f;
        if (r < NC)            v = wfc[r * NA + a];
        else if (r < 2 * NC)   v = wfct[(r - NC) * NA + a];
        g_wb[r * NA + a] = __float2bfloat16(v);
    }
}

// ---------------- y = feat @ w_fc^T + b_fc ---------------------------------
__global__ void k_y(const float* __restrict__ feat, const float* __restrict__ wfc,
                    const float* __restrict__ bfc, float* __restrict__ out) {
    int n = blockIdx.x;
    __shared__ float sf[NA];
    for (int a = threadIdx.x; a < NA; a += blockDim.x) sf[a] = feat[n * NA + a];
    __syncthreads();
    int lane = threadIdx.x & 31, wid = threadIdx.x >> 5;
    for (int c = wid; c < NC; c += 8) {
        float acc = 0.f;
        for (int a = lane; a < NA; a += 32) acc += sf[a] * wfc[c * NA + a];
        #pragma unroll
        for (int o = 16; o; o >>= 1) acc += __shfl_xor_sync(0xffffffffu, acc, o);
        if (lane == 0) out[1 + n * NC + c] = acc + bfc[c];
    }
}

// ---------------- low-rank part of new_CoV quadratic forms -----------------
__global__ void k_lowrank(const float* __restrict__ feat, const float* __restrict__ wfc,
                          const float* __restrict__ wfct) {
    int c = blockIdx.x;
    int cnt = g_cnt[c];
    if (cnt == 0) return;
    float w = g_w[c];
    float amt = (float)cnt;
    int lane = threadIdx.x & 31, wid = threadIdx.x >> 5;
    for (int idx = wid; idx < 2 * NC; idx += (int)(blockDim.x >> 5)) {
        const float* W = (idx < NC) ? wfc : wfct;
        int cp = (idx < NC) ? idx : idx - NC;
        float ssum = 0.f, dd = 0.f;
        for (int v = 0; v <= cnt; ++v) {
            float acc = 0.f;
            if (v < cnt) {
                const float* f = feat + g_items[c * 256 + v] * NA;
                for (int a = lane; a < NA; a += 32)
                    acc += (W[cp * NA + a] - W[c * NA + a]) * (f[a] - g_ave[c * NA + a]);
            } else {
                for (int a = lane; a < NA; a += 32)
                    acc += (W[cp * NA + a] - W[c * NA + a]) * g_dvec[c * NA + a];
            }
            #pragma unroll
            for (int o = 16; o; o >>= 1) acc += __shfl_xor_sync(0xffffffffu, acc, o);
            if (v < cnt) ssum += acc * acc; else dd = acc * acc;
        }
        if (lane == 0) {
            int m = (idx < NC) ? 0 : 1;
            g_qlow[m * NC * NC + c * NC + cp] = (w / amt) * ssum + w * (1.f - w) * dd;
        }
    }
}

// ---------------- big tensor-core GEMM: t1 partials -------------------------
// t1[r][c] = sum_k A[r][k]*B[c][k],  A[r][a*768+b] = Wb[r][a]*Wb[r][b],
// B[c][k] = CoV_flat[c*KTOT + k]  (already K-major contiguous).
__global__ __launch_bounds__(256, 2) void k_gemm(const float* __restrict__ CoV) {
    int mt = blockIdx.x;            // 0..3
    int nt = blockIdx.y;            // 0..1
    int ks = blockIdx.z;            // 0..KS-1
    int tid = threadIdx.x;
    int wid = tid >> 5;

    __shared__ __align__(128) __nv_bfloat16 sA[BM][BK + 8];
    __shared__ __align__(128) __nv_bfloat16 sB[BN][BK + 8];

    wmma::fragment<wmma::accumulator, 16, 16, 16, float> fc[2][4];
    #pragma unroll
    for (int i = 0; i < 2; ++i)
        #pragma unroll
        for (int j = 0; j < 4; ++j) wmma::fill_fragment(fc[i][j], 0.f);

    int wm = (wid & 3) * 32;        // warp row offset
    int wn = (wid >> 2) * 64;       // warp col offset

    int kbase0 = ks * KSPLIT;
    for (int ch = 0; ch < NCHUNK; ++ch) {
        int kb = kbase0 + ch * BK;
        int arow = kb / NA;         // BK=64 divides NA=768: chunk never straddles rows
        int b0   = kb % NA;

        // B tile: [128 classes][64 k] fp32 -> bf16
        {
            int f4 = tid & 15;      // float4 index 0..15
            int r0 = tid >> 4;      // 0..15
            #pragma unroll
            for (int rr = r0; rr < BN; rr += 16) {
                int c = nt * BN + rr;
                float4 v = make_float4(0.f, 0.f, 0.f, 0.f);
                if (c < NC)
                    v = ((const float4*)(CoV + (size_t)c * KTOT + kb))[f4];
                __nv_bfloat162* dst = (__nv_bfloat162*)&sB[rr][f4 * 4];
                dst[0] = __floats2bfloat162_rn(v.x, v.y);
                dst[1] = __floats2bfloat162_rn(v.z, v.w);
            }
        }
        // A tile (generated): sA[r][j] = Wb[gr][arow] * Wb[gr][b0+j]
        {
            int half = tid & 1;
            int r = tid >> 1;       // 0..127
            int gr = mt * BM + r;   // < 512 always valid (zero-padded)
            float s = __bfloat162float(g_wb[gr * NA + arow]);
            const __nv_bfloat162* wrow = (const __nv_bfloat162*)&g_wb[gr * NA + b0 + half * 32];
            __nv_bfloat162* dst = (__nv_bfloat162*)&sA[r][half * 32];
            #pragma unroll
            for (int j = 0; j < 16; ++j) {
                __nv_bfloat162 wv = wrow[j];
                dst[j] = __floats2bfloat162_rn(s * __bfloat162float(wv.x),
                                               s * __bfloat162float(wv.y));
            }
        }
        __syncthreads();

        #pragma unroll
        for (int kk = 0; kk < BK; kk += 16) {
            wmma::fragment<wmma::matrix_a, 16, 16, 16, __nv_bfloat16, wmma::row_major> fa[2];
            wmma::fragment<wmma::matrix_b, 16, 16, 16, __nv_bfloat16, wmma::col_major> fb[4];
            #pragma unroll
            for (int i = 0; i < 2; ++i)
                wmma::load_matrix_sync(fa[i], &sA[wm + i * 16][kk], BK + 8);
            #pragma unroll
            for (int j = 0; j < 4; ++j)
                wmma::load_matrix_sync(fb[j], &sB[wn + j * 16][kk], BK + 8);
            #pragma unroll
            for (int i = 0; i < 2; ++i)
                #pragma unroll
                for (int j = 0; j < 4; ++j)
                    wmma::mma_sync(fc[i][j], fa[i], fb[j], fc[i][j]);
        }
        __syncthreads();
    }

    float* out = g_part + (((size_t)ks * NT + nt) * 4 + mt) * (BM * BN);
    #pragma unroll
    for (int i = 0; i < 2; ++i)
        #pragma unroll
        for (int j = 0; j < 4; ++j)
            wmma::store_matrix_sync(&out[(wm + i * 16) * BN + wn + j * 16],
                                    fc[i][j], BN, wmma::mem_row_major);
}

// ---------------- deterministic split-K reduction ---------------------------
__global__ void k_reduce() {
    int idx = blockIdx.x * 256 + threadIdx.x;   // < 512*256
    int r = idx >> 8, n = idx & 255;
    int mt = r >> 7, rl = r & 127;
    int nt = n >> 7, nl = n & 127;
    float s = 0.f;
    for (int ks = 0; ks < KS; ++ks)
        s += g_part[(((size_t)ks * NT + nt) * 4 + mt) * (BM * BN) + rl * BN + nl];
    g_t1[r * 256 + n] = s;
}

// ---------------- cross/self terms: u = (M+M^T)w, self = w^T M w ------------
__global__ __launch_bounds__(256) void k_cross(const float* __restrict__ CoV,
                                               const float* __restrict__ wfc,
                                               const float* __restrict__ wfct) {
    int c = blockIdx.x;
    if (g_cnt[c] == 0) return;
    __shared__ float sw[2][NA];
    __shared__ float sv1[2][NA];
    __shared__ float sv2[2][NA];
    __shared__ float red[256];
    int tid = threadIdx.x;
    for (int a = tid; a < NA; a += 256) {
        sw[0][a] = wfc[c * NA + a];
        sw[1][a] = wfct[c * NA + a];
        sv2[0][a] = 0.f; sv2[1][a] = 0.f;
    }
    __syncthreads();
    int wid = tid >> 5, lane = tid & 31;
    float4 v2a[2][6];
    #pragma unroll
    for (int m = 0; m < 2; ++m)
        #pragma unroll
        for (int g = 0; g < 6; ++g) v2a[m][g] = make_float4(0.f, 0.f, 0.f, 0.f);

    for (int a = wid; a < NA; a += 8) {
        const float4* row = (const float4*)(CoV + (size_t)c * KTOT + (size_t)a * NA);
        float wa0 = sw[0][a], wa1 = sw[1][a];
        float d0 = 0.f, d1 = 0.f;
        #pragma unroll
        for (int g = 0; g < 6; ++g) {
            float4 mv = row[g * 32 + lane];
            int b = g * 128 + lane * 4;
            d0 += mv.x * sw[0][b] + mv.y * sw[0][b + 1] + mv.z * sw[0][b + 2] + mv.w * sw[0][b + 3];
            d1 += mv.x * sw[1][b] + mv.y * sw[1][b + 1] + mv.z * sw[1][b + 2] + mv.w * sw[1][b + 3];
            v2a[0][g].x += mv.x * wa0; v2a[0][g].y += mv.y * wa0;
            v2a[0][g].z += mv.z * wa0; v2a[0][g].w += mv.w * wa0;
            v2a[1][g].x += mv.x * wa1; v2a[1][g].y += mv.y * wa1;
            v2a[1][g].z += mv.z * wa1; v2a[1][g].w += mv.w * wa1;
        }
        #pragma unroll
        for (int o = 16; o; o >>= 1) {
            d0 += __shfl_xor_sync(0xffffffffu, d0, o);
            d1 += __shfl_xor_sync(0xffffffffu, d1, o);
        }
        if (lane == 0) { sv1[0][a] = d0; sv1[1][a] = d1; }
    }
    __syncthreads();
    // deterministic serial accumulation of column sums
    for (int wi = 0; wi < 8; ++wi) {
        if (wid == wi) {
            #pragma unroll
            for (int m = 0; m < 2; ++m)
                #pragma unroll
                for (int g = 0; g < 6; ++g) {
                    int b = g * 128 + lane * 4;
                    sv2[m][b]     += v2a[m][g].x;
                    sv2[m][b + 1] += v2a[m][g].y;
                    sv2[m][b + 2] += v2a[m][g].z;
                    sv2[m][b + 3] += v2a[m][g].w;
                }
        }
        __syncthreads();
    }
    float p0 = 0.f, p1 = 0.f;
    for (int a = tid; a < NA; a += 256) {
        g_u[(c * 2 + 0) * NA + a] = sv1[0][a] + sv2[0][a];
        g_u[(c * 2 + 1) * NA + a] = sv1[1][a] + sv2[1][a];
        p0 += sw[0][a] * sv1[0][a];
        p1 += sw[1][a] * sv1[1][a];
    }
    red[tid] = p0; __syncthreads();
    for (int s = 128; s; s >>= 1) { if (tid < s) red[tid] += red[tid + s]; __syncthreads(); }
    if (tid == 0) g_self[c * 2 + 0] = red[0];
    __syncthreads();
    red[tid] = p1; __syncthreads();
    for (int s = 128; s; s >>= 1) { if (tid < s) red[tid] += red[tid + s]; __syncthreads(); }
    if (tid == 0) g_self[c * 2 + 1] = red[0];
}

// ---------------- assemble qcov = t1 - w'.u + self --------------------------
__global__ void k_qasm(const float* __restrict__ wfc, const float* __restrict__ wfct) {
    int c = blockIdx.x;
    if (g_cnt[c] == 0) return;
    __shared__ float su[2][NA];
    int tid = threadIdx.x;
    for (int a = tid; a < NA; a += 256) {
        su[0][a] = g_u[(c * 2 + 0) * NA + a];
        su[1][a] = g_u[(c * 2 + 1) * NA + a];
    }
    __syncthreads();
    int wid = tid >> 5, lane = tid & 31;
    for (int r = wid; r < 2 * NC; r += 8) {
        int m = (r < NC) ? 0 : 1;
        int cp = (r < NC) ? r : r - NC;
        const float* W = m ? wfct : wfc;
        float acc = 0.f;
        for (int a = lane; a < NA; a += 32) acc += W[cp * NA + a] * su[m][a];
        #pragma unroll
        for (int o = 16; o; o >>= 1) acc += __shfl_xor_sync(0xffffffffu, acc, o);
        if (lane == 0)
            g_qcov[m * NC * NC + c * NC + cp] = g_t1[r * 256 + c] - acc + g_self[c * 2 + m];
    }
}

// ---------------- per-row softmax/CE/KL -------------------------------------
__device__ __forceinline__ float blk_max(float v, float* red) {
    int t = threadIdx.x;
    red[t] = v; __syncthreads();
    for (int s = 128; s; s >>= 1) { if (t < s) red[t] = fmaxf(red[t], red[t + s]); __syncthreads(); }
    float r = red[0]; __syncthreads(); return r;
}
__device__ __forceinline__ float blk_sum(float v, float* red) {
    int t = threadIdx.x;
    red[t] = v; __syncthreads();
    for (int s = 128; s; s >>= 1) { if (t < s) red[t] += red[t + s]; __syncthreads(); }
    float r = red[0]; __syncthreads(); return r;
}

__global__ void k_loss(const float* __restrict__ out, const int* __restrict__ tgt,
                       const float* __restrict__ ratio_p) {
    int n = blockIdx.x;
    int c = threadIdx.x;
    bool valid = (c < NC);
    int yn = tgt[n];
    float wy = g_w[yn];
    float ratio = ratio_p[0];
    __shared__ float red[256];

    float aug = -1e30f, augt = -1e30f;
    if (valid) {
        float yv = out[1 + n * NC + c];
        float q1 = (1.f - wy) * g_qcov[yn * NC + c] + g_qlow[yn * NC + c];
        float q2 = (1.f - wy) * g_qcov[NC * NC + yn * NC + c] + g_qlow[NC * NC + yn * NC + c];
        aug  = yv + 0.5f * ratio * q1;
        augt = yv + 0.5f * ratio * q2;
    }
    float mx  = blk_max(aug,  red);
    float mxt = blk_max(augt, red);
    float s1 = blk_sum(valid ? expf(aug  - mx)  : 0.f, red);
    float s2 = blk_sum(valid ? expf(augt - mxt) : 0.f, red);
    float l1 = logf(s1), l2 = logf(s2);
    float lp  = aug  - mx  - l1;
    float lpt = augt - mxt - l2;
    float pt  = valid ? expf(lpt) : 0.f;
    float klterm = valid ? pt * (lpt - lp) : 0.f;
    float kln = blk_sum(klterm, red);
    if (threadIdx.x == 0) g_kl[n] = kln;
    if (valid && c == yn) g_ce[n] = -lp;
}

__global__ void k_final(float* __restrict__ out) {
    __shared__ float red[256];
    int t = threadIdx.x;
    float v = g_ce[t] * (1.f / (float)NB) + g_kl[t] * (1.f / ((float)NB * (float)NC));
    red[t] = v; __syncthreads();
    for (int s = 128; s; s >>= 1) { if (t < s) red[t] += red[t + s]; __syncthreads(); }
    if (t == 0) out[0] = red[0];
}

// ---------------- launch -----------------------------------------------------
extern "C" void kernel_launch(void* const* d_in, const int* in_sizes, int n_in,
                              void* d_out, int out_size) {
    const float* feat  = (const float*)d_in[0];
    const float* wfc   = (const float*)d_in[1];
    const float* bfc   = (const float*)d_in[2];
    const float* wfct  = (const float*)d_in[3];
    const float* cov   = (const float*)d_in[4];
    const float* Ave   = (const float*)d_in[5];
    const float* Amt   = (const float*)d_in[6];
    const int*   tgt   = (const int*)d_in[7];
    const float* ratio = (const float*)d_in[8];
    float* out = (float*)d_out;

    k_stats  <<<NC, 256>>>(feat, Ave, Amt, tgt);
    k_wconv  <<<MPAD, 256>>>(wfc, wfct);
    k_y      <<<NB, 256>>>(feat, wfc, bfc, out);
    k_gemm   <<<dim3(4, NT, KS), 256>>>(cov);
    k_cross  <<<NC, 256>>>(cov, wfc, wfct);
    k_lowrank<<<NC, 256>>>(feat, wfc, wfct);
    k_reduce <<<512, 256>>>();
    k_qasm   <<<NC, 256>>>(wfc, wfct);
    k_loss   <<<NB, 256>>>(out, tgt, ratio);
    k_final  <<<1, 256>>>(out);
}

// round 5
// speedup vs baseline: 1.9781x; 1.0182x over previous
#include <cuda_runtime.h>
#include <cuda_bf16.h>
#include <mma.h>
using namespace nvcuda;

#define NC 200
#define NA 768
#define NB 256
#define KTOT (NA * NA)          // 589824
#define KS 96                   // k-splits
#define KSPLIT (KTOT / KS)      // 6144
#define BK 64
#define NCHUNK (KSPLIT / BK)    // 96
#define BM 128
#define BN 128
#define NT 2                    // n tiles (covers 256 >= 200)
#define MPAD 512

// ---------------- scratch (static device globals; no allocs) ----------------
__device__ int   g_cnt[NC];
__device__ int   g_items[NC * 256];
__device__ float g_w[NC];
__device__ float g_ave[NC * NA];
__device__ float g_dvec[NC * NA];
__device__ float g_qcov[2 * NC * NC];
__device__ float g_qlow[2 * NC * NC];
__device__ float g_ce[NB];
__device__ float g_kl[NB];
__device__ __nv_bfloat16 g_wb[MPAD * NA];            // stacked [wfc; wfct; 0] bf16
__device__ float g_part[(size_t)KS * NT * 4 * BM * BN];  // split-K partials (50.3 MB)
__device__ float g_t1[MPAD * 256];                   // t1[r][c]
__device__ float g_u[NC * 2 * NA];                   // (M+M^T) w  per (c,m)
__device__ float g_self[NC * 2];                     // w^T M w    per (c,m)

// ---------------- per-class stats ------------------------------------------
__global__ void k_stats(const float* __restrict__ feat, const float* __restrict__ Ave,
                        const float* __restrict__ Amount, const int* __restrict__ tgt) {
    int c = blockIdx.x;
    __shared__ int s_cnt;
    if (threadIdx.x == 0) {
        int k = 0;
        for (int n = 0; n < NB; ++n)
            if (tgt[n] == c) g_items[c * 256 + (k++)] = n;
        s_cnt = k;
        g_cnt[c] = k;
        float amt = (float)k;
        float den = amt + Amount[c];
        g_w[c] = (den > 0.f) ? (amt / den) : 0.f;
    }
    __syncthreads();
    int cnt = s_cnt;
    float inv = 1.f / fmaxf((float)cnt, 1.f);
    for (int a = threadIdx.x; a < NA; a += blockDim.x) {
        float s = 0.f;
        for (int k = 0; k < cnt; ++k) s += feat[g_items[c * 256 + k] * NA + a];
        float av = s * inv;
        g_ave[c * NA + a]  = av;
        g_dvec[c * NA + a] = Ave[c * NA + a] - av;
    }
}

// ---------------- bf16 stacked weights -------------------------------------
__global__ void k_wconv(const float* __restrict__ wfc, const float* __restrict__ wfct) {
    int r = blockIdx.x;
    for (int a = threadIdx.x; a < NA; a += blockDim.x) {
        float v = 0.f;
        if (r < NC)            v = wfc[r * NA + a];
        else if (r < 2 * NC)   v = wfct[(r - NC) * NA + a];
        g_wb[r * NA + a] = __float2bfloat16(v);
    }
}

// ---------------- y = feat @ w_fc^T + b_fc ---------------------------------
__global__ void k_y(const float* __restrict__ feat, const float* __restrict__ wfc,
                    const float* __restrict__ bfc, float* __restrict__ out) {
    int n = blockIdx.x;
    __shared__ float sf[NA];
    for (int a = threadIdx.x; a < NA; a += blockDim.x) sf[a] = feat[n * NA + a];
    __syncthreads();
    int lane = threadIdx.x & 31, wid = threadIdx.x >> 5;
    for (int c = wid; c < NC; c += 8) {
        float acc = 0.f;
        for (int a = lane; a < NA; a += 32) acc += sf[a] * wfc[c * NA + a];
        #pragma unroll
        for (int o = 16; o; o >>= 1) acc += __shfl_xor_sync(0xffffffffu, acc, o);
        if (lane == 0) out[1 + n * NC + c] = acc + bfc[c];
    }
}

// ---------------- low-rank part of new_CoV quadratic forms -----------------
__global__ void k_lowrank(const float* __restrict__ feat, const float* __restrict__ wfc,
                          const float* __restrict__ wfct) {
    int c = blockIdx.x;
    int cnt = g_cnt[c];
    if (cnt == 0) return;
    float w = g_w[c];
    float amt = (float)cnt;
    int lane = threadIdx.x & 31, wid = threadIdx.x >> 5;
    for (int idx = wid; idx < 2 * NC; idx += (int)(blockDim.x >> 5)) {
        const float* W = (idx < NC) ? wfc : wfct;
        int cp = (idx < NC) ? idx : idx - NC;
        float ssum = 0.f, dd = 0.f;
        for (int v = 0; v <= cnt; ++v) {
            float acc = 0.f;
            if (v < cnt) {
                const float* f = feat + g_items[c * 256 + v] * NA;
                for (int a = lane; a < NA; a += 32)
                    acc += (W[cp * NA + a] - W[c * NA + a]) * (f[a] - g_ave[c * NA + a]);
            } else {
                for (int a = lane; a < NA; a += 32)
                    acc += (W[cp * NA + a] - W[c * NA + a]) * g_dvec[c * NA + a];
            }
            #pragma unroll
            for (int o = 16; o; o >>= 1) acc += __shfl_xor_sync(0xffffffffu, acc, o);
            if (v < cnt) ssum += acc * acc; else dd = acc * acc;
        }
        if (lane == 0) {
            int m = (idx < NC) ? 0 : 1;
            g_qlow[m * NC * NC + c * NC + cp] = (w / amt) * ssum + w * (1.f - w) * dd;
        }
    }
}

// ---------------- big tensor-core GEMM: t1 partials -------------------------
// t1[r][c] = sum_k A[r][k]*B[c][k],  A[r][a*768+b] = Wb[r][a]*Wb[r][b],
// B[c][k] = CoV_flat[c*KTOT + k]  (already K-major contiguous).
__global__ __launch_bounds__(256, 2) void k_gemm(const float* __restrict__ CoV) {
    int mt = blockIdx.x;            // 0..3
    int nt = blockIdx.y;            // 0..1
    int ks = blockIdx.z;            // 0..KS-1
    int tid = threadIdx.x;
    int wid = tid >> 5;

    __shared__ __align__(128) __nv_bfloat16 sA[BM][BK + 8];
    __shared__ __align__(128) __nv_bfloat16 sB[BN][BK + 8];

    wmma::fragment<wmma::accumulator, 16, 16, 16, float> fc[2][4];
    #pragma unroll
    for (int i = 0; i < 2; ++i)
        #pragma unroll
        for (int j = 0; j < 4; ++j) wmma::fill_fragment(fc[i][j], 0.f);

    int wm = (wid & 3) * 32;        // warp row offset
    int wn = (wid >> 2) * 64;       // warp col offset

    int kbase0 = ks * KSPLIT;
    for (int ch = 0; ch < NCHUNK; ++ch) {
        int kb = kbase0 + ch * BK;
        int arow = kb / NA;         // BK=64 divides NA=768: chunk never straddles rows
        int b0   = kb % NA;

        // B tile: [128 classes][64 k] fp32 -> bf16
        {
            int f4 = tid & 15;      // float4 index 0..15
            int r0 = tid >> 4;      // 0..15
            #pragma unroll
            for (int rr = r0; rr < BN; rr += 16) {
                int c = nt * BN + rr;
                float4 v = make_float4(0.f, 0.f, 0.f, 0.f);
                if (c < NC)
                    v = ((const float4*)(CoV + (size_t)c * KTOT + kb))[f4];
                __nv_bfloat162* dst = (__nv_bfloat162*)&sB[rr][f4 * 4];
                dst[0] = __floats2bfloat162_rn(v.x, v.y);
                dst[1] = __floats2bfloat162_rn(v.z, v.w);
            }
        }
        // A tile (generated): sA[r][j] = Wb[gr][arow] * Wb[gr][b0+j]
        {
            int half = tid & 1;
            int r = tid >> 1;       // 0..127
            int gr = mt * BM + r;   // < 512 always valid (zero-padded)
            float s = __bfloat162float(g_wb[gr * NA + arow]);
            const __nv_bfloat162* wrow = (const __nv_bfloat162*)&g_wb[gr * NA + b0 + half * 32];
            __nv_bfloat162* dst = (__nv_bfloat162*)&sA[r][half * 32];
            #pragma unroll
            for (int j = 0; j < 16; ++j) {
                __nv_bfloat162 wv = wrow[j];
                dst[j] = __floats2bfloat162_rn(s * __bfloat162float(wv.x),
                                               s * __bfloat162float(wv.y));
            }
        }
        __syncthreads();

        #pragma unroll
        for (int kk = 0; kk < BK; kk += 16) {
            wmma::fragment<wmma::matrix_a, 16, 16, 16, __nv_bfloat16, wmma::row_major> fa[2];
            wmma::fragment<wmma::matrix_b, 16, 16, 16, __nv_bfloat16, wmma::col_major> fb[4];
            #pragma unroll
            for (int i = 0; i < 2; ++i)
                wmma::load_matrix_sync(fa[i], &sA[wm + i * 16][kk], BK + 8);
            #pragma unroll
            for (int j = 0; j < 4; ++j)
                wmma::load_matrix_sync(fb[j], &sB[wn + j * 16][kk], BK + 8);
            #pragma unroll
            for (int i = 0; i < 2; ++i)
                #pragma unroll
                for (int j = 0; j < 4; ++j)
                    wmma::mma_sync(fc[i][j], fa[i], fb[j], fc[i][j]);
        }
        __syncthreads();
    }

    float* out = g_part + (((size_t)ks * NT + nt) * 4 + mt) * (BM * BN);
    #pragma unroll
    for (int i = 0; i < 2; ++i)
        #pragma unroll
        for (int j = 0; j < 4; ++j)
            wmma::store_matrix_sync(&out[(wm + i * 16) * BN + wn + j * 16],
                                    fc[i][j], BN, wmma::mem_row_major);
}

// ---------------- deterministic split-K reduction ---------------------------
__global__ void k_reduce() {
    int idx = blockIdx.x * 256 + threadIdx.x;   // < 512*256
    int r = idx >> 8, n = idx & 255;
    int mt = r >> 7, rl = r & 127;
    int nt = n >> 7, nl = n & 127;
    float s = 0.f;
    for (int ks = 0; ks < KS; ++ks)
        s += g_part[(((size_t)ks * NT + nt) * 4 + mt) * (BM * BN) + rl * BN + nl];
    g_t1[r * 256 + n] = s;
}

// ---------------- cross/self terms: u = (M+M^T)w, self = w^T M w ------------
__global__ __launch_bounds__(256) void k_cross(const float* __restrict__ CoV,
                                               const float* __restrict__ wfc,
                                               const float* __restrict__ wfct) {
    int c = blockIdx.x;
    if (g_cnt[c] == 0) return;
    __shared__ float sw[2][NA];
    __shared__ float sv1[2][NA];
    __shared__ float sv2[2][NA];
    __shared__ float red[256];
    int tid = threadIdx.x;
    for (int a = tid; a < NA; a += 256) {
        sw[0][a] = wfc[c * NA + a];
        sw[1][a] = wfct[c * NA + a];
        sv2[0][a] = 0.f; sv2[1][a] = 0.f;
    }
    __syncthreads();
    int wid = tid >> 5, lane = tid & 31;
    float4 v2a[2][6];
    #pragma unroll
    for (int m = 0; m < 2; ++m)
        #pragma unroll
        for (int g = 0; g < 6; ++g) v2a[m][g] = make_float4(0.f, 0.f, 0.f, 0.f);

    for (int a = wid; a < NA; a += 8) {
        const float4* row = (const float4*)(CoV + (size_t)c * KTOT + (size_t)a * NA);
        float wa0 = sw[0][a], wa1 = sw[1][a];
        float d0 = 0.f, d1 = 0.f;
        #pragma unroll
        for (int g = 0; g < 6; ++g) {
            float4 mv = row[g * 32 + lane];
            int b = g * 128 + lane * 4;
            d0 += mv.x * sw[0][b] + mv.y * sw[0][b + 1] + mv.z * sw[0][b + 2] + mv.w * sw[0][b + 3];
            d1 += mv.x * sw[1][b] + mv.y * sw[1][b + 1] + mv.z * sw[1][b + 2] + mv.w * sw[1][b + 3];
            v2a[0][g].x += mv.x * wa0; v2a[0][g].y += mv.y * wa0;
            v2a[0][g].z += mv.z * wa0; v2a[0][g].w += mv.w * wa0;
            v2a[1][g].x += mv.x * wa1; v2a[1][g].y += mv.y * wa1;
            v2a[1][g].z += mv.z * wa1; v2a[1][g].w += mv.w * wa1;
        }
        #pragma unroll
        for (int o = 16; o; o >>= 1) {
            d0 += __shfl_xor_sync(0xffffffffu, d0, o);
            d1 += __shfl_xor_sync(0xffffffffu, d1, o);
        }
        if (lane == 0) { sv1[0][a] = d0; sv1[1][a] = d1; }
    }
    __syncthreads();
    // deterministic serial accumulation of column sums
    for (int wi = 0; wi < 8; ++wi) {
        if (wid == wi) {
            #pragma unroll
            for (int m = 0; m < 2; ++m)
                #pragma unroll
                for (int g = 0; g < 6; ++g) {
                    int b = g * 128 + lane * 4;
                    sv2[m][b]     += v2a[m][g].x;
                    sv2[m][b + 1] += v2a[m][g].y;
                    sv2[m][b + 2] += v2a[m][g].z;
                    sv2[m][b + 3] += v2a[m][g].w;
                }
        }
        __syncthreads();
    }
    float p0 = 0.f, p1 = 0.f;
    for (int a = tid; a < NA; a += 256) {
        g_u[(c * 2 + 0) * NA + a] = sv1[0][a] + sv2[0][a];
        g_u[(c * 2 + 1) * NA + a] = sv1[1][a] + sv2[1][a];
        p0 += sw[0][a] * sv1[0][a];
        p1 += sw[1][a] * sv1[1][a];
    }
    red[tid] = p0; __syncthreads();
    for (int s = 128; s; s >>= 1) { if (tid < s) red[tid] += red[tid + s]; __syncthreads(); }
    if (tid == 0) g_self[c * 2 + 0] = red[0];
    __syncthreads();
    red[tid] = p1; __syncthreads();
    for (int s = 128; s; s >>= 1) { if (tid < s) red[tid] += red[tid + s]; __syncthreads(); }
    if (tid == 0) g_self[c * 2 + 1] = red[0];
}

// ---------------- assemble qcov = t1 - w'.u + self --------------------------
__global__ void k_qasm(const float* __restrict__ wfc, const float* __restrict__ wfct) {
    int c = blockIdx.x;
    if (g_cnt[c] == 0) return;
    __shared__ float su[2][NA];
    int tid = threadIdx.x;
    for (int a = tid; a < NA; a += 256) {
        su[0][a] = g_u[(c * 2 + 0) * NA + a];
        su[1][a] = g_u[(c * 2 + 1) * NA + a];
    }
    __syncthreads();
    int wid = tid >> 5, lane = tid & 31;
    for (int r = wid; r < 2 * NC; r += 8) {
        int m = (r < NC) ? 0 : 1;
        int cp = (r < NC) ? r : r - NC;
        const float* W = m ? wfct : wfc;
        float acc = 0.f;
        for (int a = lane; a < NA; a += 32) acc += W[cp * NA + a] * su[m][a];
        #pragma unroll
        for (int o = 16; o; o >>= 1) acc += __shfl_xor_sync(0xffffffffu, acc, o);
        if (lane == 0)
            g_qcov[m * NC * NC + c * NC + cp] = g_t1[r * 256 + c] - acc + g_self[c * 2 + m];
    }
}

// ---------------- per-row softmax/CE/KL -------------------------------------
__device__ __forceinline__ float blk_max(float v, float* red) {
    int t = threadIdx.x;
    red[t] = v; __syncthreads();
    for (int s = 128; s; s >>= 1) { if (t < s) red[t] = fmaxf(red[t], red[t + s]); __syncthreads(); }
    float r = red[0]; __syncthreads(); return r;
}
__device__ __forceinline__ float blk_sum(float v, float* red) {
    int t = threadIdx.x;
    red[t] = v; __syncthreads();
    for (int s = 128; s; s >>= 1) { if (t < s) red[t] += red[t + s]; __syncthreads(); }
    float r = red[0]; __syncthreads(); return r;
}

__global__ void k_loss(const float* __restrict__ out, const int* __restrict__ tgt,
                       const float* __restrict__ ratio_p) {
    int n = blockIdx.x;
    int c = threadIdx.x;
    bool valid = (c < NC);
    int yn = tgt[n];
    float wy = g_w[yn];
    float ratio = ratio_p[0];
    __shared__ float red[256];

    float aug = -1e30f, augt = -1e30f;
    if (valid) {
        float yv = out[1 + n * NC + c];
        float q1 = (1.f - wy) * g_qcov[yn * NC + c] + g_qlow[yn * NC + c];
        float q2 = (1.f - wy) * g_qcov[NC * NC + yn * NC + c] + g_qlow[NC * NC + yn * NC + c];
        aug  = yv + 0.5f * ratio * q1;
        augt = yv + 0.5f * ratio * q2;
    }
    float mx  = blk_max(aug,  red);
    float mxt = blk_max(augt, red);
    float s1 = blk_sum(valid ? expf(aug  - mx)  : 0.f, red);
    float s2 = blk_sum(valid ? expf(augt - mxt) : 0.f, red);
    float l1 = logf(s1), l2 = logf(s2);
    float lp  = aug  - mx  - l1;
    float lpt = augt - mxt - l2;
    float pt  = valid ? expf(lpt) : 0.f;
    float klterm = valid ? pt * (lpt - lp) : 0.f;
    float kln = blk_sum(klterm, red);
    if (threadIdx.x == 0) g_kl[n] = kln;
    if (valid && c == yn) g_ce[n] = -lp;
}

__global__ void k_final(float* __restrict__ out) {
    __shared__ float red[256];
    int t = threadIdx.x;
    float v = g_ce[t] * (1.f / (float)NB) + g_kl[t] * (1.f / ((float)NB * (float)NC));
    red[t] = v; __syncthreads();
    for (int s = 128; s; s >>= 1) { if (t < s) red[t] += red[t + s]; __syncthreads(); }
    if (t == 0) out[0] = red[0];
}

// ---------------- launch -----------------------------------------------------
extern "C" void kernel_launch(void* const* d_in, const int* in_sizes, int n_in,
                              void* d_out, int out_size) {
    const float* feat  = (const float*)d_in[0];
    const float* wfc   = (const float*)d_in[1];
    const float* bfc   = (const float*)d_in[2];
    const float* wfct  = (const float*)d_in[3];
    const float* cov   = (const float*)d_in[4];
    const float* Ave   = (const float*)d_in[5];
    const float* Amt   = (const float*)d_in[6];
    const int*   tgt   = (const int*)d_in[7];
    const float* ratio = (const float*)d_in[8];
    float* out = (float*)d_out;

    k_stats  <<<NC, 256>>>(feat, Ave, Amt, tgt);
    k_wconv  <<<MPAD, 256>>>(wfc, wfct);
    k_y      <<<NB, 256>>>(feat, wfc, bfc, out);
    k_gemm   <<<dim3(4, NT, KS), 256>>>(cov);
    k_cross  <<<NC, 256>>>(cov, wfc, wfct);
    k_lowrank<<<NC, 256>>>(feat, wfc, wfct);
    k_reduce <<<512, 256>>>();
    k_qasm   <<<NC, 256>>>(wfc, wfct);
    k_loss   <<<NB, 256>>>(out, tgt, ratio);
    k_final  <<<1, 256>>>(out);
}

// round 7
// speedup vs baseline: 2.9540x; 1.4934x over previous
#include <cuda_runtime.h>
#include <cuda_bf16.h>
#include <mma.h>
#include <cstdint>
using namespace nvcuda;

#define NC 200
#define NA 768
#define NB 256
#define KTOT (NA * NA)
#define KS 96
#define MPAD 512
#define NT 2

__device__ int   g_cnt[NC];
__device__ int   g_items[NC * 256];
__device__ float g_w[NC];
__device__ float g_ave[NC * NA];
__device__ float g_dvec[NC * NA];
__device__ float g_qcov[2 * NC * NC];
__device__ float g_qlow[2 * NC * NC];
__device__ float g_ce[NB];
__device__ float g_kl[NB];
__device__ __nv_bfloat16 g_wb[MPAD * NA];
__device__ float g_part[(size_t)KS * 4 * 128 * 256];
__device__ float g_t1[MPAD * 256];
__device__ float g_u2p[(size_t)NC * 6 * 2 * NA];
__device__ float g_selfp[NC * 6 * 2];
__device__ float g_u[NC * 2 * NA];
__device__ float g_self[NC * 2];
__device__ int   g_used[256];
__device__ int   g_cidx[NC];
__device__ int   g_nused, g_npad;

__device__ __forceinline__ uint32_t f2bf2(float a, float b) {
    __nv_bfloat162 t = __floats2bfloat162_rn(a, b);
    return *(uint32_t*)&t;
}

__global__ void k_stats(const float* __restrict__ feat, const float* __restrict__ Ave,
                        const float* __restrict__ Amount, const int* __restrict__ tgt) {
    int c = blockIdx.x;
    __shared__ int s_cnt;
    if (threadIdx.x == 0) {
        int k = 0;
        for (int n = 0; n < NB; ++n)
            if (tgt[n] == c) g_items[c * 256 + (k++)] = n;
        s_cnt = k; g_cnt[c] = k;
        float amt = (float)k, den = amt + Amount[c];
        g_w[c] = (den > 0.f) ? (amt / den) : 0.f;
    }
    __syncthreads();
    int cnt = s_cnt;
    float inv = 1.f / fmaxf((float)cnt, 1.f);
    for (int a = threadIdx.x; a < NA; a += blockDim.x) {
        float s = 0.f;
        for (int k = 0; k < cnt; ++k) s += feat[g_items[c * 256 + k] * NA + a];
        float av = s * inv;
        g_ave[c * NA + a]  = av;
        g_dvec[c * NA + a] = Ave[c * NA + a] - av;
    }
}

__global__ void k_compact() {
    if (threadIdx.x == 0) {
        int nu = 0;
        for (int c = 0; c < NC; ++c) {
            if (g_cnt[c] > 0) { g_used[nu] = c; g_cidx[c] = nu; ++nu; }
            else g_cidx[c] = -1;
        }
        g_nused = nu;
        g_npad  = (nu + 15) & ~15;
    }
}

__global__ void k_wconv(const float* __restrict__ wfc, const float* __restrict__ wfct) {
    int r = blockIdx.x;
    for (int a = threadIdx.x; a < NA; a += blockDim.x) {
        float v = 0.f;
        if (r < NC)          v = wfc[r * NA + a];
        else if (r < 2 * NC) v = wfct[(r - NC) * NA + a];
        g_wb[r * NA + a] = __float2bfloat16(v);
    }
}

__global__ void k_y(const float* __restrict__ feat, const float* __restrict__ wfc,
                    const float* __restrict__ bfc, float* __restrict__ out) {
    int n = blockIdx.x;
    __shared__ float sf[NA];
    for (int a = threadIdx.x; a < NA; a += blockDim.x) sf[a] = feat[n * NA + a];
    __syncthreads();
    int lane = threadIdx.x & 31, wid = threadIdx.x >> 5;
    for (int c = wid; c < NC; c += 8) {
        float acc = 0.f;
        for (int a = lane; a < NA; a += 32) acc += sf[a] * wfc[c * NA + a];
        #pragma unroll
        for (int o = 16; o; o >>= 1) acc += __shfl_xor_sync(0xffffffffu, acc, o);
        if (lane == 0) out[1 + n * NC + c] = acc + bfc[c];
    }
}

// ---- pipelined wmma GEMM: t1 partials over compacted used classes ----------
// CTA (mt, nt, ks): tile 128(M) x 128(N), K chunk = 6144 split as 96 x 64.
// A generated on the fly from g_wb; B = CoV rows of used classes, bf16-staged.
#define LDH 72      // padded row in halves
#define BUF 18432   // 128*72*2 bytes

__global__ __launch_bounds__(256, 1) void k_gemm_w(const float* __restrict__ CoV) {
    extern __shared__ char smem[];
    const int mt = blockIdx.x, nt = blockIdx.y, ks = blockIdx.z;
    const int nused = g_nused, NP16 = g_npad;
    if (nt * 128 >= NP16) return;
    const int tid = threadIdx.x, wid = tid >> 5;
    const int wm = (wid & 3) * 32, wn = (wid >> 2) * 64;
    const int NPl = NP16 - nt * 128;
    int jmax = (NPl - wn + 15) >> 4;
    if (jmax < 0) jmax = 0; if (jmax > 4) jmax = 4;

    // B staging assignment: 16 threads per row-slot, 8 rows per thread
    const int f4 = tid & 15, r0 = tid >> 4;
    size_t bbase[8]; bool bval[8];
    #pragma unroll
    for (int k = 0; k < 8; ++k) {
        int cu = nt * 128 + r0 + 16 * k;
        bval[k]  = (cu < nused);
        bbase[k] = bval[k] ? (size_t)g_used[bval[k] ? cu : 0] * KTOT : 0;
    }
    // A staging assignment: 2 threads per row
    const int ar = tid >> 1, ah = tid & 1;
    const int gr = mt * 128 + ar;
    const __nv_bfloat16* wrow = g_wb + gr * NA;

    // zero pad rows [nused, NP16) once, both buffers
    for (int rr = nused - nt * 128 + tid / 16; rr < NPl && rr < 128; rr += 16) {
        if (rr >= 0) {
            uint4 z = make_uint4(0, 0, 0, 0);
            ((uint4*)(smem + 2 * BUF + rr * 144))[tid & 15] = z;  // 16 uint4? row=144B→9 uint4
        }
    }
    // simpler full-coverage zero of pad rows (144B each) in both buffers
    {
        int lo = nused - nt * 128; if (lo < 0) lo = 0;
        for (int idx = tid; idx < (NPl - lo) * 36; idx += 256) {
            int rr = lo + idx / 36, q = idx % 36;   // 36 uint32 per 144B row
            if (rr < 128) {
                ((uint32_t*)(smem + 2 * BUF + rr * 144))[q] = 0;
                ((uint32_t*)(smem + 3 * BUF + rr * 144))[q] = 0;
            }
        }
    }

    wmma::fragment<wmma::accumulator, 16, 16, 16, float> fc[2][4];
    #pragma unroll
    for (int i = 0; i < 2; ++i)
        #pragma unroll
        for (int j = 0; j < 4; ++j) wmma::fill_fragment(fc[i][j], 0.f);

    float4 pv[8];
    #define PREFETCH(CH) do {                                                     \
        int _arow = ks * 8 + ((CH) & 7), _b0 = ((CH) >> 3) * 64;                  \
        size_t _off = (size_t)_arow * NA + _b0 + f4 * 4;                          \
        _Pragma("unroll")                                                         \
        for (int k = 0; k < 8; ++k)                                               \
            pv[k] = bval[k] ? *(const float4*)(CoV + bbase[k] + _off)             \
                            : make_float4(0.f, 0.f, 0.f, 0.f);                    \
    } while (0)

    #define STAGE(CH, BUFSEL) do {                                                \
        int _arow = ks * 8 + ((CH) & 7), _b0 = ((CH) >> 3) * 64;                  \
        char* _sA = smem + (BUFSEL) * BUF;                                        \
        char* _sB = smem + 2 * BUF + (BUFSEL) * BUF;                              \
        /* A: products */                                                         \
        {                                                                         \
            __nv_bfloat16 _s = wrow[_arow];                                       \
            __nv_bfloat162 _s2; _s2.x = _s; _s2.y = _s;                           \
            const uint4* _wp = (const uint4*)(wrow + _b0 + ah * 32);              \
            uint4 _o[4];                                                          \
            _Pragma("unroll")                                                     \
            for (int q = 0; q < 4; ++q) {                                         \
                uint4 _w = _wp[q];                                                \
                __nv_bfloat162* _wi = (__nv_bfloat162*)&_w;                       \
                __nv_bfloat162* _oi = (__nv_bfloat162*)&_o[q];                    \
                _Pragma("unroll")                                                 \
                for (int e = 0; e < 4; ++e) _oi[e] = __hmul2(_s2, _wi[e]);        \
            }                                                                     \
            uint4* _dst = (uint4*)(_sA + ar * 144 + ah * 64);                     \
            _Pragma("unroll")                                                     \
            for (int q = 0; q < 4; ++q) _dst[q] = _o[q];                          \
        }                                                                         \
        /* B: cvt + STS */                                                        \
        _Pragma("unroll")                                                         \
        for (int k = 0; k < 8; ++k) {                                             \
            if (bval[k]) {                                                        \
                uint2 _p;                                                         \
                _p.x = f2bf2(pv[k].x, pv[k].y);                                   \
                _p.y = f2bf2(pv[k].z, pv[k].w);                                   \
                *(uint2*)(_sB + (r0 + 16 * k) * 144 + f4 * 8) = _p;               \
            }                                                                     \
        }                                                                         \
    } while (0)

    PREFETCH(0);
    STAGE(0, 0);
    PREFETCH(1);
    __syncthreads();

    for (int ch = 0; ch < 96; ++ch) {
        const int buf = ch & 1;
        if (ch + 1 < 96) STAGE(ch + 1, buf ^ 1);
        if (ch + 2 < 96) PREFETCH(ch + 2);
        const __nv_bfloat16* sA = (const __nv_bfloat16*)(smem + buf * BUF);
        const __nv_bfloat16* sB = (const __nv_bfloat16*)(smem + 2 * BUF + buf * BUF);
        if (jmax > 0) {
            #pragma unroll
            for (int kk = 0; kk < 64; kk += 16) {
                wmma::fragment<wmma::matrix_a, 16, 16, 16, __nv_bfloat16, wmma::row_major> fa[2];
                #pragma unroll
                for (int i = 0; i < 2; ++i)
                    wmma::load_matrix_sync(fa[i], sA + (wm + i * 16) * LDH + kk, LDH);
                for (int j = 0; j < jmax; ++j) {
                    wmma::fragment<wmma::matrix_b, 16, 16, 16, __nv_bfloat16, wmma::col_major> fb;
                    wmma::load_matrix_sync(fb, sB + (wn + j * 16) * LDH + kk, LDH);
                    #pragma unroll
                    for (int i = 0; i < 2; ++i)
                        wmma::mma_sync(fc[i][j], fa[i], fb, fc[i][j]);
                }
            }
        }
        __syncthreads();
    }

    float* outp = g_part + ((size_t)(ks * 4 + mt) * 128) * 256 + nt * 128;
    #pragma unroll
    for (int i = 0; i < 2; ++i)
        for (int j = 0; j < jmax; ++j)
            wmma::store_matrix_sync(outp + (wm + i * 16) * 256 + wn + j * 16,
                                    fc[i][j], 256, wmma::mem_row_major);
    #undef PREFETCH
    #undef STAGE
}

__global__ void k_reduce() {
    int idx = blockIdx.x * 256 + threadIdx.x;
    int r = idx >> 8, c = idx & 255;
    if (c >= g_npad) return;
    float s = 0.f;
    for (int ks = 0; ks < KS; ++ks)
        s += g_part[((size_t)(ks * 4 + (r >> 7)) * 128 + (r & 127)) * 256 + c];
    g_t1[r * 256 + c] = s;
}

__global__ __launch_bounds__(256) void k_cross(const float* __restrict__ CoV,
                                               const float* __restrict__ wfc,
                                               const float* __restrict__ wfct) {
    int c = blockIdx.x, y = blockIdx.y;
    if (g_cnt[c] == 0) return;
    __shared__ float sw[2][NA];
    __shared__ float sv[2][NA];
    __shared__ float srd[2][128];
    __shared__ float red[256];
    int tid = threadIdx.x;
    for (int a = tid; a < NA; a += 256) {
        sw[0][a] = wfc[c * NA + a];
        sw[1][a] = wfct[c * NA + a];
        sv[0][a] = 0.f; sv[1][a] = 0.f;
    }
    __syncthreads();
    int wid = tid >> 5, lane = tid & 31;
    float4 v2a[2][6];
    #pragma unroll
    for (int m = 0; m < 2; ++m)
        #pragma unroll
        for (int g = 0; g < 6; ++g) v2a[m][g] = make_float4(0.f, 0.f, 0.f, 0.f);
    float s0 = 0.f, s1 = 0.f;
    int abase = y * 128;
    for (int a = abase + wid; a < abase + 128; a += 8) {
        const float4* row = (const float4*)(CoV + (size_t)c * KTOT + (size_t)a * NA);
        float wa0 = sw[0][a], wa1 = sw[1][a];
        float d0 = 0.f, d1 = 0.f;
        #pragma unroll
        for (int g = 0; g < 6; ++g) {
            float4 mv = row[g * 32 + lane];
            int b = g * 128 + lane * 4;
            d0 += mv.x * sw[0][b] + mv.y * sw[0][b + 1] + mv.z * sw[0][b + 2] + mv.w * sw[0][b + 3];
            d1 += mv.x * sw[1][b] + mv.y * sw[1][b + 1] + mv.z * sw[1][b + 2] + mv.w * sw[1][b + 3];
            v2a[0][g].x += mv.x * wa0; v2a[0][g].y += mv.y * wa0;
            v2a[0][g].z += mv.z * wa0; v2a[0][g].w += mv.w * wa0;
            v2a[1][g].x += mv.x * wa1; v2a[1][g].y += mv.y * wa1;
            v2a[1][g].z += mv.z * wa1; v2a[1][g].w += mv.w * wa1;
        }
        #pragma unroll
        for (int o = 16; o; o >>= 1) {
            d0 += __shfl_xor_sync(0xffffffffu, d0, o);
            d1 += __shfl_xor_sync(0xffffffffu, d1, o);
        }
        if (lane == 0) {
            srd[0][a - abase] = d0; srd[1][a - abase] = d1;
            s0 += sw[0][a] * d0;    s1 += sw[1][a] * d1;
        }
    }
    __syncthreads();
    for (int wi = 0; wi < 8; ++wi) {
        if (wid == wi) {
            #pragma unroll
            for (int m = 0; m < 2; ++m)
                #pragma unroll
                for (int g = 0; g < 6; ++g) {
                    int b = g * 128 + lane * 4;
                    sv[m][b]     += v2a[m][g].x;
                    sv[m][b + 1] += v2a[m][g].y;
                    sv[m][b + 2] += v2a[m][g].z;
                    sv[m][b + 3] += v2a[m][g].w;
                }
        }
        __syncthreads();
    }
    for (int a = tid; a < NA; a += 256) {
        float r0v = (a >= abase && a < abase + 128) ? srd[0][a - abase] : 0.f;
        float r1v = (a >= abase && a < abase + 128) ? srd[1][a - abase] : 0.f;
        g_u2p[(((size_t)c * 6 + y) * 2 + 0) * NA + a] = sv[0][a] + r0v;
        g_u2p[(((size_t)c * 6 + y) * 2 + 1) * NA + a] = sv[1][a] + r1v;
    }
    red[tid] = s0; __syncthreads();
    for (int s = 128; s; s >>= 1) { if (tid < s) red[tid] += red[tid + s]; __syncthreads(); }
    if (tid == 0) g_selfp[(c * 6 + y) * 2 + 0] = red[0];
    __syncthreads();
    red[tid] = s1; __syncthreads();
    for (int s = 128; s; s >>= 1) { if (tid < s) red[tid] += red[tid + s]; __syncthreads(); }
    if (tid == 0) g_selfp[(c * 6 + y) * 2 + 1] = red[0];
}

__global__ void k_ucomb() {
    int c = blockIdx.x;
    if (g_cnt[c] == 0) return;
    int tid = threadIdx.x;
    for (int m = 0; m < 2; ++m)
        for (int a = tid; a < NA; a += 256) {
            float s = 0.f;
            for (int y = 0; y < 6; ++y)
                s += g_u2p[(((size_t)c * 6 + y) * 2 + m) * NA + a];
            g_u[(c * 2 + m) * NA + a] = s;
        }
    if (tid < 2) {
        float s = 0.f;
        for (int y = 0; y < 6; ++y) s += g_selfp[(c * 6 + y) * 2 + tid];
        g_self[c * 2 + tid] = s;
    }
}

__global__ void k_lowrank(const float* __restrict__ feat, const float* __restrict__ wfc,
                          const float* __restrict__ wfct) {
    int c = blockIdx.x, m = blockIdx.y;
    int cnt = g_cnt[c];
    if (cnt == 0) return;
    float w = g_w[c];
    float amt = (float)cnt;
    int lane = threadIdx.x & 31, wid = threadIdx.x >> 5;
    const float* W = m ? wfct : wfc;
    for (int cp = wid; cp < NC; cp += 8) {
        float ssum = 0.f, dd = 0.f;
        for (int v = 0; v <= cnt; ++v) {
            float acc = 0.f;
            if (v < cnt) {
                const float* f = feat + g_items[c * 256 + v] * NA;
                for (int a = lane; a < NA; a += 32)
                    acc += (W[cp * NA + a] - W[c * NA + a]) * (f[a] - g_ave[c * NA + a]);
            } else {
                for (int a = lane; a < NA; a += 32)
                    acc += (W[cp * NA + a] - W[c * NA + a]) * g_dvec[c * NA + a];
            }
            #pragma unroll
            for (int o = 16; o; o >>= 1) acc += __shfl_xor_sync(0xffffffffu, acc, o);
            if (v < cnt) ssum += acc * acc; else dd = acc * acc;
        }
        if (lane == 0)
            g_qlow[m * NC * NC + c * NC + cp] = (w / amt) * ssum + w * (1.f - w) * dd;
    }
}

__global__ void k_qasm(const float* __restrict__ wfc, const float* __restrict__ wfct) {
    int c = blockIdx.x;
    if (g_cnt[c] == 0) return;
    int cu = g_cidx[c];
    __shared__ float su[2][NA];
    int tid = threadIdx.x;
    for (int a = tid; a < NA; a += 256) {
        su[0][a] = g_u[(c * 2 + 0) * NA + a];
        su[1][a] = g_u[(c * 2 + 1) * NA + a];
    }
    __syncthreads();
    int wid = tid >> 5, lane = tid & 31;
    for (int r = wid; r < 2 * NC; r += 8) {
        int m = (r < NC) ? 0 : 1;
        int cp = (r < NC) ? r : r - NC;
        const float* W = m ? wfct : wfc;
        float acc = 0.f;
        for (int a = lane; a < NA; a += 32) acc += W[cp * NA + a] * su[m][a];
        #pragma unroll
        for (int o = 16; o; o >>= 1) acc += __shfl_xor_sync(0xffffffffu, acc, o);
        if (lane == 0)
            g_qcov[m * NC * NC + c * NC + cp] = g_t1[r * 256 + cu] - acc + g_self[c * 2 + m];
    }
}

__device__ __forceinline__ float blk_max(float v, float* red) {
    int t = threadIdx.x;
    red[t] = v; __syncthreads();
    for (int s = 128; s; s >>= 1) { if (t < s) red[t] = fmaxf(red[t], red[t + s]); __syncthreads(); }
    float r = red[0]; __syncthreads(); return r;
}
__device__ __forceinline__ float blk_sum(float v, float* red) {
    int t = threadIdx.x;
    red[t] = v; __syncthreads();
    for (int s = 128; s; s >>= 1) { if (t < s) red[t] += red[t + s]; __syncthreads(); }
    float r = red[0]; __syncthreads(); return r;
}

__global__ void k_loss(const float* __restrict__ out, const int* __restrict__ tgt,
                       const float* __restrict__ ratio_p) {
    int n = blockIdx.x;
    int c = threadIdx.x;
    bool valid = (c < NC);
    int yn = tgt[n];
    float wy = g_w[yn];
    float ratio = ratio_p[0];
    __shared__ float red[256];
    float aug = -1e30f, augt = -1e30f;
    if (valid) {
        float yv = out[1 + n * NC + c];
        float q1 = (1.f - wy) * g_qcov[yn * NC + c] + g_qlow[yn * NC + c];
        float q2 = (1.f - wy) * g_qcov[NC * NC + yn * NC + c] + g_qlow[NC * NC + yn * NC + c];
        aug  = yv + 0.5f * ratio * q1;
        augt = yv + 0.5f * ratio * q2;
    }
    float mx  = blk_max(aug,  red);
    float mxt = blk_max(augt, red);
    float sa = blk_sum(valid ? expf(aug  - mx)  : 0.f, red);
    float sb = blk_sum(valid ? expf(augt - mxt) : 0.f, red);
    float lp  = aug  - mx  - logf(sa);
    float lpt = augt - mxt - logf(sb);
    float pt  = valid ? expf(lpt) : 0.f;
    float kln = blk_sum(valid ? pt * (lpt - lp) : 0.f, red);
    if (threadIdx.x == 0) g_kl[n] = kln;
    if (valid && c == yn) g_ce[n] = -lp;
}

__global__ void k_final(float* __restrict__ out) {
    __shared__ float red[256];
    int t = threadIdx.x;
    float v = g_ce[t] * (1.f / (float)NB) + g_kl[t] * (1.f / ((float)NB * (float)NC));
    red[t] = v; __syncthreads();
    for (int s = 128; s; s >>= 1) { if (t < s) red[t] += red[t + s]; __syncthreads(); }
    if (t == 0) out[0] = red[0];
}

extern "C" void kernel_launch(void* const* d_in, const int* in_sizes, int n_in,
                              void* d_out, int out_size) {
    const float* feat  = (const float*)d_in[0];
    const float* wfc   = (const float*)d_in[1];
    const float* bfc   = (const float*)d_in[2];
    const float* wfct  = (const float*)d_in[3];
    const float* cov   = (const float*)d_in[4];
    const float* Ave   = (const float*)d_in[5];
    const float* Amt   = (const float*)d_in[6];
    const int*   tgt   = (const int*)d_in[7];
    const float* ratio = (const float*)d_in[8];
    float* out = (float*)d_out;

    static bool attr_set = false;
    if (!attr_set) {
        cudaFuncSetAttribute(k_gemm_w, cudaFuncAttributeMaxDynamicSharedMemorySize, 4 * BUF);
        attr_set = true;
    }

    k_stats  <<<NC, 256>>>(feat, Ave, Amt, tgt);
    k_compact<<<1, 32>>>();
    k_wconv  <<<MPAD, 256>>>(wfc, wfct);
    k_y      <<<NB, 256>>>(feat, wfc, bfc, out);
    k_gemm_w <<<dim3(4, NT, KS), 256, 4 * BUF>>>(cov);
    k_cross  <<<dim3(NC, 6), 256>>>(cov, wfc, wfct);
    k_lowrank<<<dim3(NC, 2), 256>>>(feat, wfc, wfct);
    k_reduce <<<512, 256>>>();
    k_ucomb  <<<NC, 256>>>();
    k_qasm   <<<NC, 256>>>(wfc, wfct);
    k_loss   <<<NB, 256>>>(out, tgt, ratio);
    k_final  <<<1, 256>>>(out);
}

// round 8
// speedup vs baseline: 3.7049x; 1.2542x over previous
#include <cuda_runtime.h>
#include <cuda_bf16.h>
#include <mma.h>
#include <cstdint>
using namespace nvcuda;

#define NC 200
#define NA 768
#define NB 256
#define KTOT (NA * NA)
#define KS 96
#define MPAD 512
#define NT 2

__device__ int   g_cnt[NC];
__device__ int   g_items[NC * 256];
__device__ float g_w[NC];
__device__ float g_ave[NC * NA];
__device__ float g_dvec[NC * NA];
__device__ float g_qcov[2 * NC * NC];
__device__ float g_qlow[2 * NC * NC];
__device__ float g_ce[NB];
__device__ float g_kl[NB];
__device__ __nv_bfloat16 g_wb[MPAD * NA];
__device__ float g_part[(size_t)KS * 4 * 128 * 256];
__device__ float g_t1[MPAD * 256];
__device__ float g_u2p[(size_t)NC * 6 * 2 * NA];
__device__ float g_selfp[NC * 6 * 2];
__device__ float g_u[NC * 2 * NA];
__device__ float g_self[NC * 2];
__device__ int   g_used[256];
__device__ int   g_cidx[NC];
__device__ int   g_nused, g_npad;

__device__ __forceinline__ uint32_t f2bf2(float a, float b) {
    __nv_bfloat162 t = __floats2bfloat162_rn(a, b);
    return *(uint32_t*)&t;
}

__global__ void k_stats(const float* __restrict__ feat, const float* __restrict__ Ave,
                        const float* __restrict__ Amount, const int* __restrict__ tgt) {
    int c = blockIdx.x;
    __shared__ int s_cnt;
    if (threadIdx.x == 0) {
        int k = 0;
        for (int n = 0; n < NB; ++n)
            if (tgt[n] == c) g_items[c * 256 + (k++)] = n;
        s_cnt = k; g_cnt[c] = k;
        float amt = (float)k, den = amt + Amount[c];
        g_w[c] = (den > 0.f) ? (amt / den) : 0.f;
    }
    __syncthreads();
    int cnt = s_cnt;
    float inv = 1.f / fmaxf((float)cnt, 1.f);
    for (int a = threadIdx.x; a < NA; a += blockDim.x) {
        float s = 0.f;
        for (int k = 0; k < cnt; ++k) s += feat[g_items[c * 256 + k] * NA + a];
        float av = s * inv;
        g_ave[c * NA + a]  = av;
        g_dvec[c * NA + a] = Ave[c * NA + a] - av;
    }
}

__global__ void k_compact() {
    if (threadIdx.x == 0) {
        int nu = 0;
        for (int c = 0; c < NC; ++c) {
            if (g_cnt[c] > 0) { g_used[nu] = c; g_cidx[c] = nu; ++nu; }
            else g_cidx[c] = -1;
        }
        g_nused = nu;
        g_npad  = (nu + 15) & ~15;
    }
}

__global__ void k_wconv(const float* __restrict__ wfc, const float* __restrict__ wfct) {
    int r = blockIdx.x;
    for (int a = threadIdx.x; a < NA; a += blockDim.x) {
        float v = 0.f;
        if (r < NC)          v = wfc[r * NA + a];
        else if (r < 2 * NC) v = wfct[(r - NC) * NA + a];
        g_wb[r * NA + a] = __float2bfloat16(v);
    }
}

// ---- y = feat @ w_fc^T + b_fc, 8 rows per CTA ------------------------------
__global__ void k_y(const float* __restrict__ feat, const float* __restrict__ wfc,
                    const float* __restrict__ bfc, float* __restrict__ out) {
    int n0 = blockIdx.x * 8;
    __shared__ float sf[8][NA];
    int tid = threadIdx.x;
    for (int idx = tid; idx < 8 * NA; idx += 256)
        sf[idx / NA][idx % NA] = feat[(n0 + idx / NA) * NA + idx % NA];
    __syncthreads();
    int lane = tid & 31, wid = tid >> 5;
    for (int c = wid; c < NC; c += 8) {
        float wreg[24];
        #pragma unroll
        for (int i = 0; i < 24; ++i) wreg[i] = wfc[c * NA + i * 32 + lane];
        float bc = bfc[c];
        for (int r = 0; r < 8; ++r) {
            float acc = 0.f;
            #pragma unroll
            for (int i = 0; i < 24; ++i) acc += wreg[i] * sf[r][i * 32 + lane];
            #pragma unroll
            for (int o = 16; o; o >>= 1) acc += __shfl_xor_sync(0xffffffffu, acc, o);
            if (lane == 0) out[1 + (n0 + r) * NC + c] = acc + bc;
        }
    }
}

// ---- pipelined wmma GEMM: t1 partials over compacted used classes ----------
#define LDH 72
#define BUF 18432

__global__ __launch_bounds__(256, 2) void k_gemm_w(const float* __restrict__ CoV) {
    extern __shared__ char smem[];
    const int mt = blockIdx.x, nt = blockIdx.y, ks = blockIdx.z;
    const int nused = g_nused, NP16 = g_npad;
    if (nt * 128 >= NP16) return;
    const int tid = threadIdx.x, wid = tid >> 5;
    const int wm = (wid & 3) * 32, wn = (wid >> 2) * 64;
    const int NPl = NP16 - nt * 128;
    int jmax = (NPl - wn + 15) >> 4;
    if (jmax < 0) jmax = 0; if (jmax > 4) jmax = 4;
    // valid M rows: < 2*NC = 400
    int imax = (400 - (mt * 128 + wm) + 15) >> 4;
    if (imax < 0) imax = 0; if (imax > 2) imax = 2;

    const int f4 = tid & 15, r0 = tid >> 4;
    size_t bbase[8]; bool bval[8];
    #pragma unroll
    for (int k = 0; k < 8; ++k) {
        int cu = nt * 128 + r0 + 16 * k;
        bval[k]  = (cu < nused);
        bbase[k] = bval[k] ? (size_t)g_used[bval[k] ? cu : 0] * KTOT : 0;
    }
    const int ar = tid >> 1, ah = tid & 1;
    const int gr = mt * 128 + ar;
    const __nv_bfloat16* wrow = g_wb + gr * NA;

    // zero pad rows [nused, NP16) in both B buffers (144B rows, 36 u32 each)
    {
        int lo = nused - nt * 128; if (lo < 0) lo = 0;
        for (int idx = tid; idx < (NPl - lo) * 36; idx += 256) {
            int rr = lo + idx / 36, q = idx % 36;
            if (rr < 128) {
                ((uint32_t*)(smem + 2 * BUF + rr * 144))[q] = 0;
                ((uint32_t*)(smem + 3 * BUF + rr * 144))[q] = 0;
            }
        }
    }

    wmma::fragment<wmma::accumulator, 16, 16, 16, float> fc[2][4];
    #pragma unroll
    for (int i = 0; i < 2; ++i)
        #pragma unroll
        for (int j = 0; j < 4; ++j) wmma::fill_fragment(fc[i][j], 0.f);

    float4 pv[8];
    #define PREFETCH(CH) do {                                                     \
        int _arow = ks * 8 + ((CH) & 7), _b0 = ((CH) >> 3) * 64;                  \
        size_t _off = (size_t)_arow * NA + _b0 + f4 * 4;                          \
        _Pragma("unroll")                                                         \
        for (int k = 0; k < 8; ++k)                                               \
            pv[k] = bval[k] ? *(const float4*)(CoV + bbase[k] + _off)             \
                            : make_float4(0.f, 0.f, 0.f, 0.f);                    \
    } while (0)

    #define STAGE(CH, BUFSEL) do {                                                \
        int _arow = ks * 8 + ((CH) & 7), _b0 = ((CH) >> 3) * 64;                  \
        char* _sA = smem + (BUFSEL) * BUF;                                        \
        char* _sB = smem + 2 * BUF + (BUFSEL) * BUF;                              \
        {                                                                         \
            __nv_bfloat16 _s = wrow[_arow];                                       \
            __nv_bfloat162 _s2; _s2.x = _s; _s2.y = _s;                           \
            const uint4* _wp = (const uint4*)(wrow + _b0 + ah * 32);              \
            uint4 _o[4];                                                          \
            _Pragma("unroll")                                                     \
            for (int q = 0; q < 4; ++q) {                                         \
                uint4 _w = _wp[q];                                                \
                __nv_bfloat162* _wi = (__nv_bfloat162*)&_w;                       \
                __nv_bfloat162* _oi = (__nv_bfloat162*)&_o[q];                    \
                _Pragma("unroll")                                                 \
                for (int e = 0; e < 4; ++e) _oi[e] = __hmul2(_s2, _wi[e]);        \
            }                                                                     \
            uint4* _dst = (uint4*)(_sA + ar * 144 + ah * 64);                     \
            _Pragma("unroll")                                                     \
            for (int q = 0; q < 4; ++q) _dst[q] = _o[q];                          \
        }                                                                         \
        _Pragma("unroll")                                                         \
        for (int k = 0; k < 8; ++k) {                                             \
            if (bval[k]) {                                                        \
                uint2 _p;                                                         \
                _p.x = f2bf2(pv[k].x, pv[k].y);                                   \
                _p.y = f2bf2(pv[k].z, pv[k].w);                                   \
                *(uint2*)(_sB + (r0 + 16 * k) * 144 + f4 * 8) = _p;               \
            }                                                                     \
        }                                                                         \
    } while (0)

    PREFETCH(0);
    STAGE(0, 0);
    PREFETCH(1);
    __syncthreads();

    for (int ch = 0; ch < 96; ++ch) {
        const int buf = ch & 1;
        if (ch + 1 < 96) STAGE(ch + 1, buf ^ 1);
        if (ch + 2 < 96) PREFETCH(ch + 2);
        const __nv_bfloat16* sA = (const __nv_bfloat16*)(smem + buf * BUF);
        const __nv_bfloat16* sB = (const __nv_bfloat16*)(smem + 2 * BUF + buf * BUF);
        if (jmax > 0 && imax > 0) {
            #pragma unroll
            for (int kk = 0; kk < 64; kk += 16) {
                wmma::fragment<wmma::matrix_a, 16, 16, 16, __nv_bfloat16, wmma::row_major> fa[2];
                for (int i = 0; i < imax; ++i)
                    wmma::load_matrix_sync(fa[i], sA + (wm + i * 16) * LDH + kk, LDH);
                for (int j = 0; j < jmax; ++j) {
                    wmma::fragment<wmma::matrix_b, 16, 16, 16, __nv_bfloat16, wmma::col_major> fb;
                    wmma::load_matrix_sync(fb, sB + (wn + j * 16) * LDH + kk, LDH);
                    for (int i = 0; i < imax; ++i)
                        wmma::mma_sync(fc[i][j], fa[i], fb, fc[i][j]);
                }
            }
        }
        __syncthreads();
    }

    float* outp = g_part + ((size_t)(ks * 4 + mt) * 128) * 256 + nt * 128;
    for (int i = 0; i < imax; ++i)
        for (int j = 0; j < jmax; ++j)
            wmma::store_matrix_sync(outp + (wm + i * 16) * 256 + wn + j * 16,
                                    fc[i][j], 256, wmma::mem_row_major);
    #undef PREFETCH
    #undef STAGE
}

__global__ void k_reduce() {
    int idx = blockIdx.x * 256 + threadIdx.x;
    int r = idx >> 8, c = idx & 255;
    if (c >= g_npad || r >= 400) return;
    float s = 0.f;
    for (int ks = 0; ks < KS; ++ks)
        s += g_part[((size_t)(ks * 4 + (r >> 7)) * 128 + (r & 127)) * 256 + c];
    g_t1[r * 256 + c] = s;
}

__global__ __launch_bounds__(256) void k_cross(const float* __restrict__ CoV,
                                               const float* __restrict__ wfc,
                                               const float* __restrict__ wfct) {
    int c = blockIdx.x, y = blockIdx.y;
    if (g_cnt[c] == 0) return;
    __shared__ float sw[2][NA];
    __shared__ float sv[2][NA];
    __shared__ float srd[2][128];
    __shared__ float red[256];
    int tid = threadIdx.x;
    for (int a = tid; a < NA; a += 256) {
        sw[0][a] = wfc[c * NA + a];
        sw[1][a] = wfct[c * NA + a];
        sv[0][a] = 0.f; sv[1][a] = 0.f;
    }
    __syncthreads();
    int wid = tid >> 5, lane = tid & 31;
    float4 v2a[2][6];
    #pragma unroll
    for (int m = 0; m < 2; ++m)
        #pragma unroll
        for (int g = 0; g < 6; ++g) v2a[m][g] = make_float4(0.f, 0.f, 0.f, 0.f);
    float s0 = 0.f, s1 = 0.f;
    int abase = y * 128;
    for (int a = abase + wid; a < abase + 128; a += 8) {
        const float4* row = (const float4*)(CoV + (size_t)c * KTOT + (size_t)a * NA);
        float wa0 = sw[0][a], wa1 = sw[1][a];
        float d0 = 0.f, d1 = 0.f;
        #pragma unroll
        for (int g = 0; g < 6; ++g) {
            float4 mv = row[g * 32 + lane];
            int b = g * 128 + lane * 4;
            d0 += mv.x * sw[0][b] + mv.y * sw[0][b + 1] + mv.z * sw[0][b + 2] + mv.w * sw[0][b + 3];
            d1 += mv.x * sw[1][b] + mv.y * sw[1][b + 1] + mv.z * sw[1][b + 2] + mv.w * sw[1][b + 3];
            v2a[0][g].x += mv.x * wa0; v2a[0][g].y += mv.y * wa0;
            v2a[0][g].z += mv.z * wa0; v2a[0][g].w += mv.w * wa0;
            v2a[1][g].x += mv.x * wa1; v2a[1][g].y += mv.y * wa1;
            v2a[1][g].z += mv.z * wa1; v2a[1][g].w += mv.w * wa1;
        }
        #pragma unroll
        for (int o = 16; o; o >>= 1) {
            d0 += __shfl_xor_sync(0xffffffffu, d0, o);
            d1 += __shfl_xor_sync(0xffffffffu, d1, o);
        }
        if (lane == 0) {
            srd[0][a - abase] = d0; srd[1][a - abase] = d1;
            s0 += sw[0][a] * d0;    s1 += sw[1][a] * d1;
        }
    }
    __syncthreads();
    for (int wi = 0; wi < 8; ++wi) {
        if (wid == wi) {
            #pragma unroll
            for (int m = 0; m < 2; ++m)
                #pragma unroll
                for (int g = 0; g < 6; ++g) {
                    int b = g * 128 + lane * 4;
                    sv[m][b]     += v2a[m][g].x;
                    sv[m][b + 1] += v2a[m][g].y;
                    sv[m][b + 2] += v2a[m][g].z;
                    sv[m][b + 3] += v2a[m][g].w;
                }
        }
        __syncthreads();
    }
    for (int a = tid; a < NA; a += 256) {
        float r0v = (a >= abase && a < abase + 128) ? srd[0][a - abase] : 0.f;
        float r1v = (a >= abase && a < abase + 128) ? srd[1][a - abase] : 0.f;
        g_u2p[(((size_t)c * 6 + y) * 2 + 0) * NA + a] = sv[0][a] + r0v;
        g_u2p[(((size_t)c * 6 + y) * 2 + 1) * NA + a] = sv[1][a] + r1v;
    }
    red[tid] = s0; __syncthreads();
    for (int s = 128; s; s >>= 1) { if (tid < s) red[tid] += red[tid + s]; __syncthreads(); }
    if (tid == 0) g_selfp[(c * 6 + y) * 2 + 0] = red[0];
    __syncthreads();
    red[tid] = s1; __syncthreads();
    for (int s = 128; s; s >>= 1) { if (tid < s) red[tid] += red[tid + s]; __syncthreads(); }
    if (tid == 0) g_selfp[(c * 6 + y) * 2 + 1] = red[0];
}

__global__ void k_ucomb() {
    int c = blockIdx.x;
    if (g_cnt[c] == 0) return;
    int tid = threadIdx.x;
    for (int m = 0; m < 2; ++m)
        for (int a = tid; a < NA; a += 256) {
            float s = 0.f;
            for (int y = 0; y < 6; ++y)
                s += g_u2p[(((size_t)c * 6 + y) * 2 + m) * NA + a];
            g_u[(c * 2 + m) * NA + a] = s;
        }
    if (tid < 2) {
        float s = 0.f;
        for (int y = 0; y < 6; ++y) s += g_selfp[(c * 6 + y) * 2 + tid];
        g_self[c * 2 + tid] = s;
    }
}

__global__ void k_lowrank(const float* __restrict__ feat, const float* __restrict__ wfc,
                          const float* __restrict__ wfct) {
    int c = blockIdx.x, m = blockIdx.y;
    int cnt = g_cnt[c];
    if (cnt == 0) return;
    float w = g_w[c];
    float amt = (float)cnt;
    int lane = threadIdx.x & 31, wid = threadIdx.x >> 5;
    const float* W = m ? wfct : wfc;
    for (int cp = wid; cp < NC; cp += 8) {
        float ssum = 0.f, dd = 0.f;
        for (int v = 0; v <= cnt; ++v) {
            float acc = 0.f;
            if (v < cnt) {
                const float* f = feat + g_items[c * 256 + v] * NA;
                for (int a = lane; a < NA; a += 32)
                    acc += (W[cp * NA + a] - W[c * NA + a]) * (f[a] - g_ave[c * NA + a]);
            } else {
                for (int a = lane; a < NA; a += 32)
                    acc += (W[cp * NA + a] - W[c * NA + a]) * g_dvec[c * NA + a];
            }
            #pragma unroll
            for (int o = 16; o; o >>= 1) acc += __shfl_xor_sync(0xffffffffu, acc, o);
            if (v < cnt) ssum += acc * acc; else dd = acc * acc;
        }
        if (lane == 0)
            g_qlow[m * NC * NC + c * NC + cp] = (w / amt) * ssum + w * (1.f - w) * dd;
    }
}

__global__ void k_qasm(const float* __restrict__ wfc, const float* __restrict__ wfct) {
    int c = blockIdx.x;
    if (g_cnt[c] == 0) return;
    int cu = g_cidx[c];
    __shared__ float su[2][NA];
    int tid = threadIdx.x;
    for (int a = tid; a < NA; a += 256) {
        su[0][a] = g_u[(c * 2 + 0) * NA + a];
        su[1][a] = g_u[(c * 2 + 1) * NA + a];
    }
    __syncthreads();
    int wid = tid >> 5, lane = tid & 31;
    for (int r = wid; r < 2 * NC; r += 8) {
        int m = (r < NC) ? 0 : 1;
        int cp = (r < NC) ? r : r - NC;
        const float* W = m ? wfct : wfc;
        float acc = 0.f;
        for (int a = lane; a < NA; a += 32) acc += W[cp * NA + a] * su[m][a];
        #pragma unroll
        for (int o = 16; o; o >>= 1) acc += __shfl_xor_sync(0xffffffffu, acc, o);
        if (lane == 0)
            g_qcov[m * NC * NC + c * NC + cp] = g_t1[r * 256 + cu] - acc + g_self[c * 2 + m];
    }
}

__device__ __forceinline__ float blk_max(float v, float* red) {
    int t = threadIdx.x;
    red[t] = v; __syncthreads();
    for (int s = 128; s; s >>= 1) { if (t < s) red[t] = fmaxf(red[t], red[t + s]); __syncthreads(); }
    float r = red[0]; __syncthreads(); return r;
}
__device__ __forceinline__ float blk_sum(float v, float* red) {
    int t = threadIdx.x;
    red[t] = v; __syncthreads();
    for (int s = 128; s; s >>= 1) { if (t < s) red[t] += red[t + s]; __syncthreads(); }
    float r = red[0]; __syncthreads(); return r;
}

__global__ void k_loss(const float* __restrict__ out, const int* __restrict__ tgt,
                       const float* __restrict__ ratio_p) {
    int n = blockIdx.x;
    int c = threadIdx.x;
    bool valid = (c < NC);
    int yn = tgt[n];
    float wy = g_w[yn];
    float ratio = ratio_p[0];
    __shared__ float red[256];
    float aug = -1e30f, augt = -1e30f;
    if (valid) {
        float yv = out[1 + n * NC + c];
        float q1 = (1.f - wy) * g_qcov[yn * NC + c] + g_qlow[yn * NC + c];
        float q2 = (1.f - wy) * g_qcov[NC * NC + yn * NC + c] + g_qlow[NC * NC + yn * NC + c];
        aug  = yv + 0.5f * ratio * q1;
        augt = yv + 0.5f * ratio * q2;
    }
    float mx  = blk_max(aug,  red);
    float mxt = blk_max(augt, red);
    float sa = blk_sum(valid ? expf(aug  - mx)  : 0.f, red);
    float sb = blk_sum(valid ? expf(augt - mxt) : 0.f, red);
    float lp  = aug  - mx  - logf(sa);
    float lpt = augt - mxt - logf(sb);
    float pt  = valid ? expf(lpt) : 0.f;
    float kln = blk_sum(valid ? pt * (lpt - lp) : 0.f, red);
    if (threadIdx.x == 0) g_kl[n] = kln;
    if (valid && c == yn) g_ce[n] = -lp;
}

__global__ void k_final(float* __restrict__ out) {
    __shared__ float red[256];
    int t = threadIdx.x;
    float v = g_ce[t] * (1.f / (float)NB) + g_kl[t] * (1.f / ((float)NB * (float)NC));
    red[t] = v; __syncthreads();
    for (int s = 128; s; s >>= 1) { if (t < s) red[t] += red[t + s]; __syncthreads(); }
    if (t == 0) out[0] = red[0];
}

extern "C" void kernel_launch(void* const* d_in, const int* in_sizes, int n_in,
                              void* d_out, int out_size) {
    const float* feat  = (const float*)d_in[0];
    const float* wfc   = (const float*)d_in[1];
    const float* bfc   = (const float*)d_in[2];
    const float* wfct  = (const float*)d_in[3];
    const float* cov   = (const float*)d_in[4];
    const float* Ave   = (const float*)d_in[5];
    const float* Amt   = (const float*)d_in[6];
    const int*   tgt   = (const int*)d_in[7];
    const float* ratio = (const float*)d_in[8];
    float* out = (float*)d_out;

    static bool init_done = false;
    static cudaStream_t sB, sC;
    static cudaEvent_t evFork, evB, evC;
    if (!init_done) {
        cudaFuncSetAttribute(k_gemm_w, cudaFuncAttributeMaxDynamicSharedMemorySize, 4 * BUF);
        cudaStreamCreateWithFlags(&sB, cudaStreamNonBlocking);
        cudaStreamCreateWithFlags(&sC, cudaStreamNonBlocking);
        cudaEventCreateWithFlags(&evFork, cudaEventDisableTiming);
        cudaEventCreateWithFlags(&evB, cudaEventDisableTiming);
        cudaEventCreateWithFlags(&evC, cudaEventDisableTiming);
        init_done = true;
    }

    // stream 0: stats -> compact -> fork
    k_stats  <<<NC, 256>>>(feat, Ave, Amt, tgt);
    k_compact<<<1, 32>>>();
    cudaEventRecord(evFork, 0);

    // stream B: cross path (DRAM-bound), independent of wconv/gemm
    cudaStreamWaitEvent(sB, evFork, 0);
    k_cross  <<<dim3(NC, 6), 256, 0, sB>>>(cov, wfc, wfct);
    k_ucomb  <<<NC, 256, 0, sB>>>();
    cudaEventRecord(evB, sB);

    // stream C: y + lowrank (fma/latency-bound)
    cudaStreamWaitEvent(sC, evFork, 0);
    k_y      <<<32, 256, 0, sC>>>(feat, wfc, bfc, out);
    k_lowrank<<<dim3(NC, 2), 256, 0, sC>>>(feat, wfc, wfct);
    cudaEventRecord(evC, sC);

    // stream 0: gemm path (tensor/L1-bound)
    k_wconv  <<<MPAD, 256>>>(wfc, wfct);
    k_gemm_w <<<dim3(4, NT, KS), 256, 4 * BUF>>>(cov);
    k_reduce <<<512, 256>>>();

    // join
    cudaStreamWaitEvent(0, evB, 0);
    k_qasm   <<<NC, 256>>>(wfc, wfct);
    cudaStreamWaitEvent(0, evC, 0);
    k_loss   <<<NB, 256>>>(out, tgt, ratio);
    k_final  <<<1, 256>>>(out);
}

// round 9
// speedup vs baseline: 4.3006x; 1.1608x over previous
#include <cuda_runtime.h>
#include <cuda_bf16.h>
#include <mma.h>
#include <cstdint>
using namespace nvcuda;

#define NC 200
#define NA 768
#define NB 256
#define KTOT (NA * NA)
#define MPAD 512

__device__ int   g_cnt[NC];
__device__ int   g_items[NC * 256];
__device__ float g_w[NC];
__device__ float g_ave[NC * NA];
__device__ float g_dvec[NC * NA];
__device__ float g_qcov[2 * NC * NC];
__device__ float g_qlow[2 * NC * NC];
__device__ float g_ce[NB];
__device__ float g_kl[NB];
__device__ float g_ws[MPAD * NA];
__device__ __nv_bfloat16 g_wb[MPAD * NA];
__device__ __nv_bfloat16 g_covh[(size_t)NC * KTOT];   // bf16 CoV copy
__device__ float g_D[(size_t)NC * 400 * NA];          // D_c[r][a] = (M_c w_r)[a]

__device__ __forceinline__ uint32_t f2bf2(float a, float b) {
    __nv_bfloat162 t = __floats2bfloat162_rn(a, b);
    return *(uint32_t*)&t;
}

__global__ void k_stats(const float* __restrict__ feat, const float* __restrict__ Ave,
                        const float* __restrict__ Amount, const int* __restrict__ tgt) {
    int c = blockIdx.x;
    __shared__ int s_cnt;
    if (threadIdx.x == 0) {
        int k = 0;
        for (int n = 0; n < NB; ++n)
            if (tgt[n] == c) g_items[c * 256 + (k++)] = n;
        s_cnt = k; g_cnt[c] = k;
        float amt = (float)k, den = amt + Amount[c];
        g_w[c] = (den > 0.f) ? (amt / den) : 0.f;
    }
    __syncthreads();
    int cnt = s_cnt;
    float inv = 1.f / fmaxf((float)cnt, 1.f);
    for (int a = threadIdx.x; a < NA; a += blockDim.x) {
        float s = 0.f;
        for (int k = 0; k < cnt; ++k) s += feat[g_items[c * 256 + k] * NA + a];
        float av = s * inv;
        g_ave[c * NA + a]  = av;
        g_dvec[c * NA + a] = Ave[c * NA + a] - av;
    }
}

__global__ void k_wconv(const float* __restrict__ wfc, const float* __restrict__ wfct) {
    int r = blockIdx.x;
    for (int a = threadIdx.x; a < NA; a += blockDim.x) {
        float v = 0.f;
        if (r < NC)          v = wfc[r * NA + a];
        else if (r < 2 * NC) v = wfct[(r - NC) * NA + a];
        g_ws[r * NA + a] = v;
        g_wb[r * NA + a] = __float2bfloat16(v);
    }
}

// ---- CoV fp32 -> bf16, all classes. grid (NC, 36), 16384 floats per CTA ----
__global__ void k_covcvt(const float* __restrict__ CoV) {
    size_t cbase = (size_t)blockIdx.x * KTOT;
    const float4* src = (const float4*)(CoV + cbase) + blockIdx.y * 4096;
    uint2* dst = (uint2*)(g_covh + cbase) + blockIdx.y * 4096;
    int tid = threadIdx.x;
    #pragma unroll
    for (int k = 0; k < 16; ++k) {
        float4 v = src[tid + k * 256];
        uint2 p;
        p.x = f2bf2(v.x, v.y);
        p.y = f2bf2(v.z, v.w);
        dst[tid + k * 256] = p;
    }
}

// ---- y = feat @ w_fc^T + b_fc, 8 rows per CTA ------------------------------
__global__ void k_y(const float* __restrict__ feat, const float* __restrict__ wfc,
                    const float* __restrict__ bfc, float* __restrict__ out) {
    int n0 = blockIdx.x * 8;
    __shared__ float sf[8][NA];
    int tid = threadIdx.x;
    for (int idx = tid; idx < 8 * NA; idx += 256)
        sf[idx / NA][idx % NA] = feat[(n0 + idx / NA) * NA + idx % NA];
    __syncthreads();
    int lane = tid & 31, wid = tid >> 5;
    for (int c = wid; c < NC; c += 8) {
        float wreg[24];
        #pragma unroll
        for (int i = 0; i < 24; ++i) wreg[i] = wfc[c * NA + i * 32 + lane];
        float bc = bfc[c];
        for (int r = 0; r < 8; ++r) {
            float acc = 0.f;
            #pragma unroll
            for (int i = 0; i < 24; ++i) acc += wreg[i] * sf[r][i * 32 + lane];
            #pragma unroll
            for (int o = 16; o; o >>= 1) acc += __shfl_xor_sync(0xffffffffu, acc, o);
            if (lane == 0) out[1 + (n0 + r) * NC + c] = acc + bc;
        }
    }
}

// ---- batched GEMM: D_c[r][a] = sum_b covh[c][a][b] * wb[r][b] --------------
// grid (24, NC): tile = 24 -> at(6 a-tiles of 128) x rt(4 r-tiles of 128)
// K = 768, 12 chunks of 64, cp.async double-buffered, pure HMMA.
#define SMBUF 18432   // 128 rows * 144B
#define LDH 72

__global__ __launch_bounds__(256, 2) void k_gemm2() {
    extern __shared__ char smem[];
    const int c = blockIdx.y;
    if (g_cnt[c] == 0) return;
    const int at = blockIdx.x >> 2, rt = blockIdx.x & 3;
    const int tid = threadIdx.x, wid = tid >> 5;
    const int wm = (wid & 3) * 32, wn = (wid >> 2) * 64;
    const int row = tid >> 1, half = tid & 1;
    const uint32_t sbase = (uint32_t)__cvta_generic_to_shared(smem);

    const char* srcA = (const char*)g_covh +
        2 * ((size_t)c * KTOT + (size_t)(at * 128 + row) * NA + half * 32);
    const char* srcB = (const char*)g_wb +
        2 * ((size_t)(rt * 128 + row) * NA + half * 32);
    const uint32_t dA = sbase + row * 144 + half * 64;
    const uint32_t dB = sbase + SMBUF + row * 144 + half * 64;

    #define ISSUE(CH) do {                                                       \
        uint32_t _o = ((CH) & 1) * (2 * SMBUF);                                  \
        const char* _sa = srcA + (size_t)(CH) * 128;                             \
        const char* _sb = srcB + (size_t)(CH) * 128;                             \
        _Pragma("unroll")                                                        \
        for (int q = 0; q < 4; ++q) {                                            \
            asm volatile("cp.async.cg.shared.global [%0], [%1], 16;"             \
                :: "r"(dA + _o + q * 16), "l"(_sa + q * 16));                    \
            asm volatile("cp.async.cg.shared.global [%0], [%1], 16;"             \
                :: "r"(dB + _o + q * 16), "l"(_sb + q * 16));                    \
        }                                                                        \
        asm volatile("cp.async.commit_group;");                                  \
    } while (0)

    wmma::fragment<wmma::accumulator, 16, 16, 16, float> fc[2][4];
    #pragma unroll
    for (int i = 0; i < 2; ++i)
        #pragma unroll
        for (int j = 0; j < 4; ++j) wmma::fill_fragment(fc[i][j], 0.f);

    ISSUE(0);
    for (int ch = 0; ch < 12; ++ch) {
        if (ch < 11) {
            ISSUE(ch + 1);
            asm volatile("cp.async.wait_group 1;");
        } else {
            asm volatile("cp.async.wait_group 0;");
        }
        __syncthreads();
        const __nv_bfloat16* sA = (const __nv_bfloat16*)(smem + (ch & 1) * (2 * SMBUF));
        const __nv_bfloat16* sB = (const __nv_bfloat16*)(smem + (ch & 1) * (2 * SMBUF) + SMBUF);
        #pragma unroll
        for (int kk = 0; kk < 64; kk += 16) {
            wmma::fragment<wmma::matrix_a, 16, 16, 16, __nv_bfloat16, wmma::row_major> fa[2];
            #pragma unroll
            for (int i = 0; i < 2; ++i)
                wmma::load_matrix_sync(fa[i], sA + (wm + i * 16) * LDH + kk, LDH);
            #pragma unroll
            for (int j = 0; j < 4; ++j) {
                wmma::fragment<wmma::matrix_b, 16, 16, 16, __nv_bfloat16, wmma::col_major> fb;
                wmma::load_matrix_sync(fb, sB + (wn + j * 16) * LDH + kk, LDH);
                #pragma unroll
                for (int i = 0; i < 2; ++i)
                    wmma::mma_sync(fc[i][j], fa[i], fb, fc[i][j]);
            }
        }
        __syncthreads();
    }
    #undef ISSUE

    // store col-major: element (a, r) at D[c][r][a]; skip frags with r >= 400
    float* Dc = g_D + (size_t)c * 400 * NA;
    #pragma unroll
    for (int i = 0; i < 2; ++i)
        #pragma unroll
        for (int j = 0; j < 4; ++j) {
            int r0 = rt * 128 + wn + j * 16;
            if (r0 < 400)
                wmma::store_matrix_sync(Dc + (size_t)r0 * NA + at * 128 + wm + i * 16,
                                        fc[i][j], NA, wmma::mem_col_major);
        }
}

// ---- epilogue: qcov[m][c][cp] = t1 - cross1 - cross2 + self ---------------
__global__ __launch_bounds__(256) void k_post() {
    int c = blockIdx.x;
    if (g_cnt[c] == 0) return;
    int rbase = blockIdx.y * 100;
    int tid = threadIdx.x, lane = tid & 31, wid = tid >> 5;
    __shared__ float sw[2][NA];
    __shared__ float sd[2][NA];
    __shared__ float red[256];
    __shared__ float s_self[2];
    const float* D0 = g_D + ((size_t)c * 400 + c) * NA;
    const float* D1 = g_D + ((size_t)c * 400 + NC + c) * NA;
    for (int a = tid; a < NA; a += 256) {
        sw[0][a] = g_ws[c * NA + a];
        sw[1][a] = g_ws[(NC + c) * NA + a];
        sd[0][a] = D0[a];
        sd[1][a] = D1[a];
    }
    __syncthreads();
    for (int m = 0; m < 2; ++m) {
        float p = 0.f;
        for (int a = tid; a < NA; a += 256) p += sw[m][a] * sd[m][a];
        red[tid] = p; __syncthreads();
        for (int s = 128; s; s >>= 1) { if (tid < s) red[tid] += red[tid + s]; __syncthreads(); }
        if (tid == 0) s_self[m] = red[0];
        __syncthreads();
    }
    for (int r = rbase + wid; r < rbase + 100; r += 8) {
        int m = (r < NC) ? 0 : 1;
        int cp = r - m * NC;
        const float* Dr = g_D + ((size_t)c * 400 + r) * NA;
        const float* Wr = g_ws + r * NA;
        float t1 = 0.f, c1 = 0.f, c2 = 0.f;
        for (int a = lane; a < NA; a += 32) {
            float dv = Dr[a], wv = Wr[a];
            t1 += wv * dv;
            c2 += sw[m][a] * dv;
            c1 += wv * sd[m][a];
        }
        #pragma unroll
        for (int o = 16; o; o >>= 1) {
            t1 += __shfl_xor_sync(0xffffffffu, t1, o);
            c1 += __shfl_xor_sync(0xffffffffu, c1, o);
            c2 += __shfl_xor_sync(0xffffffffu, c2, o);
        }
        if (lane == 0)
            g_qcov[m * NC * NC + c * NC + cp] = t1 - c1 - c2 + s_self[m];
    }
}

__global__ void k_lowrank(const float* __restrict__ feat, const float* __restrict__ wfc,
                          const float* __restrict__ wfct) {
    int c = blockIdx.x, m = blockIdx.y;
    int cnt = g_cnt[c];
    if (cnt == 0) return;
    float w = g_w[c];
    float amt = (float)cnt;
    int lane = threadIdx.x & 31, wid = threadIdx.x >> 5;
    const float* W = m ? wfct : wfc;
    for (int cp = wid; cp < NC; cp += 8) {
        float ssum = 0.f, dd = 0.f;
        for (int v = 0; v <= cnt; ++v) {
            float acc = 0.f;
            if (v < cnt) {
                const float* f = feat + g_items[c * 256 + v] * NA;
                for (int a = lane; a < NA; a += 32)
                    acc += (W[cp * NA + a] - W[c * NA + a]) * (f[a] - g_ave[c * NA + a]);
            } else {
                for (int a = lane; a < NA; a += 32)
                    acc += (W[cp * NA + a] - W[c * NA + a]) * g_dvec[c * NA + a];
            }
            #pragma unroll
            for (int o = 16; o; o >>= 1) acc += __shfl_xor_sync(0xffffffffu, acc, o);
            if (v < cnt) ssum += acc * acc; else dd = acc * acc;
        }
        if (lane == 0)
            g_qlow[m * NC * NC + c * NC + cp] = (w / amt) * ssum + w * (1.f - w) * dd;
    }
}

__device__ __forceinline__ float blk_max(float v, float* red) {
    int t = threadIdx.x;
    red[t] = v; __syncthreads();
    for (int s = 128; s; s >>= 1) { if (t < s) red[t] = fmaxf(red[t], red[t + s]); __syncthreads(); }
    float r = red[0]; __syncthreads(); return r;
}
__device__ __forceinline__ float blk_sum(float v, float* red) {
    int t = threadIdx.x;
    red[t] = v; __syncthreads();
    for (int s = 128; s; s >>= 1) { if (t < s) red[t] += red[t + s]; __syncthreads(); }
    float r = red[0]; __syncthreads(); return r;
}

__global__ void k_loss(const float* __restrict__ out, const int* __restrict__ tgt,
                       const float* __restrict__ ratio_p) {
    int n = blockIdx.x;
    int c = threadIdx.x;
    bool valid = (c < NC);
    int yn = tgt[n];
    float wy = g_w[yn];
    float ratio = ratio_p[0];
    __shared__ float red[256];
    float aug = -1e30f, augt = -1e30f;
    if (valid) {
        float yv = out[1 + n * NC + c];
        float q1 = (1.f - wy) * g_qcov[yn * NC + c] + g_qlow[yn * NC + c];
        float q2 = (1.f - wy) * g_qcov[NC * NC + yn * NC + c] + g_qlow[NC * NC + yn * NC + c];
        aug  = yv + 0.5f * ratio * q1;
        augt = yv + 0.5f * ratio * q2;
    }
    float mx  = blk_max(aug,  red);
    float mxt = blk_max(augt, red);
    float sa = blk_sum(valid ? expf(aug  - mx)  : 0.f, red);
    float sb = blk_sum(valid ? expf(augt - mxt) : 0.f, red);
    float lp  = aug  - mx  - logf(sa);
    float lpt = augt - mxt - logf(sb);
    float pt  = valid ? expf(lpt) : 0.f;
    float kln = blk_sum(valid ? pt * (lpt - lp) : 0.f, red);
    if (threadIdx.x == 0) g_kl[n] = kln;
    if (valid && c == yn) g_ce[n] = -lp;
}

__global__ void k_final(float* __restrict__ out) {
    __shared__ float red[256];
    int t = threadIdx.x;
    float v = g_ce[t] * (1.f / (float)NB) + g_kl[t] * (1.f / ((float)NB * (float)NC));
    red[t] = v; __syncthreads();
    for (int s = 128; s; s >>= 1) { if (t < s) red[t] += red[t + s]; __syncthreads(); }
    if (t == 0) out[0] = red[0];
}

extern "C" void kernel_launch(void* const* d_in, const int* in_sizes, int n_in,
                              void* d_out, int out_size) {
    const float* feat  = (const float*)d_in[0];
    const float* wfc   = (const float*)d_in[1];
    const float* bfc   = (const float*)d_in[2];
    const float* wfct  = (const float*)d_in[3];
    const float* cov   = (const float*)d_in[4];
    const float* Ave   = (const float*)d_in[5];
    const float* Amt   = (const float*)d_in[6];
    const int*   tgt   = (const int*)d_in[7];
    const float* ratio = (const float*)d_in[8];
    float* out = (float*)d_out;

    static bool init_done = false;
    static cudaStream_t sB;
    static cudaEvent_t evFork, evStats, evC;
    if (!init_done) {
        cudaFuncSetAttribute(k_gemm2, cudaFuncAttributeMaxDynamicSharedMemorySize, 4 * SMBUF);
        cudaStreamCreateWithFlags(&sB, cudaStreamNonBlocking);
        cudaEventCreateWithFlags(&evFork, cudaEventDisableTiming);
        cudaEventCreateWithFlags(&evStats, cudaEventDisableTiming);
        cudaEventCreateWithFlags(&evC, cudaEventDisableTiming);
        init_done = true;
    }

    cudaEventRecord(evFork, 0);

    // side stream: stats -> (y, lowrank)
    cudaStreamWaitEvent(sB, evFork, 0);
    k_stats  <<<NC, 256, 0, sB>>>(feat, Ave, Amt, tgt);
    cudaEventRecord(evStats, sB);
    k_y      <<<32, 256, 0, sB>>>(feat, wfc, bfc, out);
    k_lowrank<<<dim3(NC, 2), 256, 0, sB>>>(feat, wfc, wfct);
    cudaEventRecord(evC, sB);

    // main stream: wconv -> covcvt -> gemm2 -> post -> loss -> final
    k_wconv  <<<MPAD, 256>>>(wfc, wfct);
    k_covcvt <<<dim3(NC, 36), 256>>>(cov);
    cudaStreamWaitEvent(0, evStats, 0);
    k_gemm2  <<<dim3(24, NC), 256, 4 * SMBUF>>>();
    k_post   <<<dim3(NC, 4), 256>>>();
    cudaStreamWaitEvent(0, evC, 0);
    k_loss   <<<NB, 256>>>(out, tgt, ratio);
    k_final  <<<1, 256>>>(out);
}

// round 10
// speedup vs baseline: 4.6837x; 1.0891x over previous
#include <cuda_runtime.h>
#include <cuda_bf16.h>
#include <mma.h>
#include <cstdint>
using namespace nvcuda;

#define NC 200
#define NA 768
#define NB 256
#define KTOT (NA * NA)
#define MPAD 512

__device__ int   g_cnt[NC];
__device__ int   g_items[NC * 256];
__device__ float g_w[NC];
__device__ float g_ave[NC * NA];
__device__ float g_dvec[NC * NA];
__device__ float g_qcov[2 * NC * NC];
__device__ float g_qlow[2 * NC * NC];
__device__ float g_ce[NB];
__device__ float g_kl[NB];
__device__ float g_ws[MPAD * NA];
__device__ __nv_bfloat16 g_wb[MPAD * NA];
__device__ __nv_bfloat16 g_covh[(size_t)NC * KTOT];
__device__ float g_D[(size_t)NC * 400 * NA];

__device__ __forceinline__ uint32_t f2bf2(float a, float b) {
    __nv_bfloat162 t = __floats2bfloat162_rn(a, b);
    return *(uint32_t*)&t;
}

__global__ void k_stats(const float* __restrict__ feat, const float* __restrict__ Ave,
                        const float* __restrict__ Amount, const int* __restrict__ tgt) {
    int c = blockIdx.x;
    __shared__ int s_cnt;
    if (threadIdx.x == 0) {
        int k = 0;
        for (int n = 0; n < NB; ++n)
            if (tgt[n] == c) g_items[c * 256 + (k++)] = n;
        s_cnt = k; g_cnt[c] = k;
        float amt = (float)k, den = amt + Amount[c];
        g_w[c] = (den > 0.f) ? (amt / den) : 0.f;
    }
    __syncthreads();
    int cnt = s_cnt;
    float inv = 1.f / fmaxf((float)cnt, 1.f);
    for (int a = threadIdx.x; a < NA; a += blockDim.x) {
        float s = 0.f;
        for (int k = 0; k < cnt; ++k) s += feat[g_items[c * 256 + k] * NA + a];
        float av = s * inv;
        g_ave[c * NA + a]  = av;
        g_dvec[c * NA + a] = Ave[c * NA + a] - av;
    }
}

__global__ void k_wconv(const float* __restrict__ wfc, const float* __restrict__ wfct) {
    int r = blockIdx.x;
    for (int a = threadIdx.x; a < NA; a += blockDim.x) {
        float v = 0.f;
        if (r < NC)          v = wfc[r * NA + a];
        else if (r < 2 * NC) v = wfct[(r - NC) * NA + a];
        g_ws[r * NA + a] = v;
        g_wb[r * NA + a] = __float2bfloat16(v);
    }
}

// ---- CoV fp32 -> bf16, used classes only -----------------------------------
__global__ void k_covcvt(const float* __restrict__ CoV) {
    if (g_cnt[blockIdx.x] == 0) return;
    size_t cbase = (size_t)blockIdx.x * KTOT;
    const float4* src = (const float4*)(CoV + cbase) + blockIdx.y * 4096;
    uint2* dst = (uint2*)(g_covh + cbase) + blockIdx.y * 4096;
    int tid = threadIdx.x;
    #pragma unroll
    for (int k = 0; k < 16; ++k) {
        float4 v = src[tid + k * 256];
        uint2 p;
        p.x = f2bf2(v.x, v.y);
        p.y = f2bf2(v.z, v.w);
        dst[tid + k * 256] = p;
    }
}

__global__ void k_y(const float* __restrict__ feat, const float* __restrict__ wfc,
                    const float* __restrict__ bfc, float* __restrict__ out) {
    int n0 = blockIdx.x * 8;
    __shared__ float sf[8][NA];
    int tid = threadIdx.x;
    for (int idx = tid; idx < 8 * NA; idx += 256)
        sf[idx / NA][idx % NA] = feat[(n0 + idx / NA) * NA + idx % NA];
    __syncthreads();
    int lane = tid & 31, wid = tid >> 5;
    for (int c = wid; c < NC; c += 8) {
        float wreg[24];
        #pragma unroll
        for (int i = 0; i < 24; ++i) wreg[i] = wfc[c * NA + i * 32 + lane];
        float bc = bfc[c];
        for (int r = 0; r < 8; ++r) {
            float acc = 0.f;
            #pragma unroll
            for (int i = 0; i < 24; ++i) acc += wreg[i] * sf[r][i * 32 + lane];
            #pragma unroll
            for (int o = 16; o; o >>= 1) acc += __shfl_xor_sync(0xffffffffu, acc, o);
            if (lane == 0) out[1 + (n0 + r) * NC + c] = acc + bc;
        }
    }
}

// ---- batched GEMM: D_c[r][a] = sum_b covh[c][a][b] * wb[r][b] --------------
// grid (12, NC): at = x>>1 (6 a-tiles of 128), rt = x&1 (2 r-tiles of 256)
// warp tile 64a x 64r; K = 768 in 12 chunks of 64; cp.async double buffer.
#define ABUF 18432            // 128 * 144B
#define BBUF 36864            // 256 * 144B
#define CBUF (ABUF + BBUF)    // 55296 per stage
#define LDH 72

__global__ __launch_bounds__(256) void k_gemm2() {
    extern __shared__ char smem[];
    const int c = blockIdx.y;
    if (g_cnt[c] == 0) return;
    const int at = blockIdx.x >> 1, rt = blockIdx.x & 1;
    const int tid = threadIdx.x, wid = tid >> 5;
    const int wm = (wid & 1) * 64;          // a offset in tile
    const int wn = (wid >> 1) * 64;         // r offset in tile
    int rlim = 400 - (rt * 256 + wn);
    int jmax = (rlim + 15) >> 4;
    if (jmax < 0) jmax = 0; if (jmax > 4) jmax = 4;

    const int rowA = tid >> 1, halfA = tid & 1;
    const uint32_t sbase = (uint32_t)__cvta_generic_to_shared(smem);
    const char* srcA = (const char*)g_covh +
        2 * ((size_t)c * KTOT + (size_t)(at * 128 + rowA) * NA) + halfA * 64;
    const char* srcB = (const char*)g_wb + 2 * (size_t)(rt * 256 + tid) * NA;
    const uint32_t dA = sbase + rowA * 144 + halfA * 64;
    const uint32_t dB = sbase + ABUF + tid * 144;

    #define ISSUE(CH) do {                                                       \
        uint32_t _o = ((CH) & 1) * CBUF;                                         \
        const char* _sa = srcA + (size_t)(CH) * 128;                             \
        const char* _sb = srcB + (size_t)(CH) * 128;                             \
        _Pragma("unroll")                                                        \
        for (int q = 0; q < 4; ++q)                                              \
            asm volatile("cp.async.cg.shared.global [%0], [%1], 16;"             \
                :: "r"(dA + _o + q * 16), "l"(_sa + q * 16));                    \
        _Pragma("unroll")                                                        \
        for (int q = 0; q < 8; ++q)                                              \
            asm volatile("cp.async.cg.shared.global [%0], [%1], 16;"             \
                :: "r"(dB + _o + q * 16), "l"(_sb + q * 16));                    \
        asm volatile("cp.async.commit_group;");                                  \
    } while (0)

    wmma::fragment<wmma::accumulator, 16, 16, 16, float> fc[4][4];
    #pragma unroll
    for (int i = 0; i < 4; ++i)
        #pragma unroll
        for (int j = 0; j < 4; ++j) wmma::fill_fragment(fc[i][j], 0.f);

    ISSUE(0);
    for (int ch = 0; ch < 12; ++ch) {
        if (ch < 11) {
            ISSUE(ch + 1);
            asm volatile("cp.async.wait_group 1;");
        } else {
            asm volatile("cp.async.wait_group 0;");
        }
        __syncthreads();
        const __nv_bfloat16* sA = (const __nv_bfloat16*)(smem + (ch & 1) * CBUF);
        const __nv_bfloat16* sB = (const __nv_bfloat16*)(smem + (ch & 1) * CBUF + ABUF);
        if (jmax > 0) {
            #pragma unroll
            for (int kk = 0; kk < 64; kk += 16) {
                wmma::fragment<wmma::matrix_a, 16, 16, 16, __nv_bfloat16, wmma::row_major> fa[4];
                #pragma unroll
                for (int i = 0; i < 4; ++i)
                    wmma::load_matrix_sync(fa[i], sA + (wm + i * 16) * LDH + kk, LDH);
                for (int j = 0; j < jmax; ++j) {
                    wmma::fragment<wmma::matrix_b, 16, 16, 16, __nv_bfloat16, wmma::col_major> fb;
                    wmma::load_matrix_sync(fb, sB + (wn + j * 16) * LDH + kk, LDH);
                    #pragma unroll
                    for (int i = 0; i < 4; ++i)
                        wmma::mma_sync(fc[i][j], fa[i], fb, fc[i][j]);
                }
            }
        }
        __syncthreads();
    }
    #undef ISSUE

    float* Dc = g_D + (size_t)c * 400 * NA;
    for (int j = 0; j < jmax; ++j) {
        int r0 = rt * 256 + wn + j * 16;
        if (r0 < 400) {
            #pragma unroll
            for (int i = 0; i < 4; ++i)
                wmma::store_matrix_sync(Dc + (size_t)r0 * NA + at * 128 + wm + i * 16,
                                        fc[i][j], NA, wmma::mem_col_major);
        }
    }
}

// ---- epilogue: qcov = t1 - cross1 - cross2 + self --------------------------
__global__ __launch_bounds__(256) void k_post() {
    int c = blockIdx.x;
    if (g_cnt[c] == 0) return;
    int rbase = blockIdx.y * 100;
    int tid = threadIdx.x, lane = tid & 31, wid = tid >> 5;
    __shared__ float sw[2][NA];
    __shared__ float sd[2][NA];
    __shared__ float red[256];
    __shared__ float s_self[2];
    const float* D0 = g_D + ((size_t)c * 400 + c) * NA;
    const float* D1 = g_D + ((size_t)c * 400 + NC + c) * NA;
    for (int a = tid; a < NA; a += 256) {
        sw[0][a] = g_ws[c * NA + a];
        sw[1][a] = g_ws[(NC + c) * NA + a];
        sd[0][a] = D0[a];
        sd[1][a] = D1[a];
    }
    __syncthreads();
    for (int m = 0; m < 2; ++m) {
        float p = 0.f;
        for (int a = tid; a < NA; a += 256) p += sw[m][a] * sd[m][a];
        red[tid] = p; __syncthreads();
        for (int s = 128; s; s >>= 1) { if (tid < s) red[tid] += red[tid + s]; __syncthreads(); }
        if (tid == 0) s_self[m] = red[0];
        __syncthreads();
    }
    for (int r = rbase + wid; r < rbase + 100; r += 8) {
        int m = (r < NC) ? 0 : 1;
        int cp = r - m * NC;
        const float* Dr = g_D + ((size_t)c * 400 + r) * NA;
        const float* Wr = g_ws + r * NA;
        float t1 = 0.f, c1 = 0.f, c2 = 0.f;
        for (int a = lane; a < NA; a += 32) {
            float dv = Dr[a], wv = Wr[a];
            t1 += wv * dv;
            c2 += sw[m][a] * dv;
            c1 += wv * sd[m][a];
        }
        #pragma unroll
        for (int o = 16; o; o >>= 1) {
            t1 += __shfl_xor_sync(0xffffffffu, t1, o);
            c1 += __shfl_xor_sync(0xffffffffu, c1, o);
            c2 += __shfl_xor_sync(0xffffffffu, c2, o);
        }
        if (lane == 0)
            g_qcov[m * NC * NC + c * NC + cp] = t1 - c1 - c2 + s_self[m];
    }
}

__global__ void k_lowrank(const float* __restrict__ feat, const float* __restrict__ wfc,
                          const float* __restrict__ wfct) {
    int c = blockIdx.x, m = blockIdx.y;
    int cnt = g_cnt[c];
    if (cnt == 0) return;
    float w = g_w[c];
    float amt = (float)cnt;
    int lane = threadIdx.x & 31, wid = threadIdx.x >> 5;
    const float* W = m ? wfct : wfc;
    for (int cp = wid; cp < NC; cp += 8) {
        float ssum = 0.f, dd = 0.f;
        for (int v = 0; v <= cnt; ++v) {
            float acc = 0.f;
            if (v < cnt) {
                const float* f = feat + g_items[c * 256 + v] * NA;
                for (int a = lane; a < NA; a += 32)
                    acc += (W[cp * NA + a] - W[c * NA + a]) * (f[a] - g_ave[c * NA + a]);
            } else {
                for (int a = lane; a < NA; a += 32)
                    acc += (W[cp * NA + a] - W[c * NA + a]) * g_dvec[c * NA + a];
            }
            #pragma unroll
            for (int o = 16; o; o >>= 1) acc += __shfl_xor_sync(0xffffffffu, acc, o);
            if (v < cnt) ssum += acc * acc; else dd = acc * acc;
        }
        if (lane == 0)
            g_qlow[m * NC * NC + c * NC + cp] = (w / amt) * ssum + w * (1.f - w) * dd;
    }
}

__device__ __forceinline__ float blk_max(float v, float* red) {
    int t = threadIdx.x;
    red[t] = v; __syncthreads();
    for (int s = 128; s; s >>= 1) { if (t < s) red[t] = fmaxf(red[t], red[t + s]); __syncthreads(); }
    float r = red[0]; __syncthreads(); return r;
}
__device__ __forceinline__ float blk_sum(float v, float* red) {
    int t = threadIdx.x;
    red[t] = v; __syncthreads();
    for (int s = 128; s; s >>= 1) { if (t < s) red[t] += red[t + s]; __syncthreads(); }
    float r = red[0]; __syncthreads(); return r;
}

__global__ void k_loss(const float* __restrict__ out, const int* __restrict__ tgt,
                       const float* __restrict__ ratio_p) {
    int n = blockIdx.x;
    int c = threadIdx.x;
    bool valid = (c < NC);
    int yn = tgt[n];
    float wy = g_w[yn];
    float ratio = ratio_p[0];
    __shared__ float red[256];
    float aug = -1e30f, augt = -1e30f;
    if (valid) {
        float yv = out[1 + n * NC + c];
        float q1 = (1.f - wy) * g_qcov[yn * NC + c] + g_qlow[yn * NC + c];
        float q2 = (1.f - wy) * g_qcov[NC * NC + yn * NC + c] + g_qlow[NC * NC + yn * NC + c];
        aug  = yv + 0.5f * ratio * q1;
        augt = yv + 0.5f * ratio * q2;
    }
    float mx  = blk_max(aug,  red);
    float mxt = blk_max(augt, red);
    float sa = blk_sum(valid ? expf(aug  - mx)  : 0.f, red);
    float sb = blk_sum(valid ? expf(augt - mxt) : 0.f, red);
    float lp  = aug  - mx  - logf(sa);
    float lpt = augt - mxt - logf(sb);
    float pt  = valid ? expf(lpt) : 0.f;
    float kln = blk_sum(valid ? pt * (lpt - lp) : 0.f, red);
    if (threadIdx.x == 0) g_kl[n] = kln;
    if (valid && c == yn) g_ce[n] = -lp;
}

__global__ void k_final(float* __restrict__ out) {
    __shared__ float red[256];
    int t = threadIdx.x;
    float v = g_ce[t] * (1.f / (float)NB) + g_kl[t] * (1.f / ((float)NB * (float)NC));
    red[t] = v; __syncthreads();
    for (int s = 128; s; s >>= 1) { if (t < s) red[t] += red[t + s]; __syncthreads(); }
    if (t == 0) out[0] = red[0];
}

extern "C" void kernel_launch(void* const* d_in, const int* in_sizes, int n_in,
                              void* d_out, int out_size) {
    const float* feat  = (const float*)d_in[0];
    const float* wfc   = (const float*)d_in[1];
    const float* bfc   = (const float*)d_in[2];
    const float* wfct  = (const float*)d_in[3];
    const float* cov   = (const float*)d_in[4];
    const float* Ave   = (const float*)d_in[5];
    const float* Amt   = (const float*)d_in[6];
    const int*   tgt   = (const int*)d_in[7];
    const float* ratio = (const float*)d_in[8];
    float* out = (float*)d_out;

    static bool init_done = false;
    static cudaStream_t sB;
    static cudaEvent_t evFork, evStats, evC;
    if (!init_done) {
        cudaFuncSetAttribute(k_gemm2, cudaFuncAttributeMaxDynamicSharedMemorySize, 2 * CBUF);
        cudaStreamCreateWithFlags(&sB, cudaStreamNonBlocking);
        cudaEventCreateWithFlags(&evFork, cudaEventDisableTiming);
        cudaEventCreateWithFlags(&evStats, cudaEventDisableTiming);
        cudaEventCreateWithFlags(&evC, cudaEventDisableTiming);
        init_done = true;
    }

    cudaEventRecord(evFork, 0);

    // main stream: stats -> wconv -> covcvt -> gemm2 -> post
    k_stats  <<<NC, 256>>>(feat, Ave, Amt, tgt);
    cudaEventRecord(evStats, 0);
    k_wconv  <<<MPAD, 256>>>(wfc, wfct);
    k_covcvt <<<dim3(NC, 36), 256>>>(cov);
    k_gemm2  <<<dim3(12, NC), 256, 2 * CBUF>>>();
    k_post   <<<dim3(NC, 4), 256>>>();

    // side stream: y (independent), then lowrank (needs stats)
    cudaStreamWaitEvent(sB, evFork, 0);
    k_y      <<<32, 256, 0, sB>>>(feat, wfc, bfc, out);
    cudaStreamWaitEvent(sB, evStats, 0);
    k_lowrank<<<dim3(NC, 2), 256, 0, sB>>>(feat, wfc, wfct);
    cudaEventRecord(evC, sB);

    cudaStreamWaitEvent(0, evC, 0);
    k_loss   <<<NB, 256>>>(out, tgt, ratio);
    k_final  <<<1, 256>>>(out);
}